// round 13
// baseline (speedup 1.0000x reference)
#include <cuda_runtime.h>
#include <cuda_bf16.h>
#include <cuda_fp16.h>
#include <math.h>
#include <stdint.h>

#define BB 2
#define SS 1024
#define HH 768
#define NH 12
#define DH 64
#define FF 3072
#define NL 4

// ---------------- scratch (device globals; no allocation allowed) ----------------
__device__ float g_h[BB*SS*HH];
__device__ float g_attn[BB*SS*HH];
__device__ float g_p0[BB*SS*HH];
__device__ float g_p1[BB*SS*HH];
__device__ float g_p2[BB*SS*HH];

__device__ __half g_hh[BB*SS*HH], g_hl[BB*SS*HH];
__device__ __half g_qh[BB*SS*HH], g_ql[BB*SS*HH];
__device__ __half g_kh[BB*SS*HH], g_kl[BB*SS*HH];
__device__ __half g_vh[BB*SS*HH], g_vl[BB*SS*HH];
__device__ __half g_cth[BB*SS*HH], g_ctl[BB*SS*HH];
__device__ __half g_aah[BB*SS*HH], g_aal[BB*SS*HH];
__device__ __half g_ih[BB*SS*FF], g_il[BB*SS*FF];
__device__ __nv_bfloat16 g_madd[(size_t)BB*SS*SS];   // (1-mask)*-10000 as bf16

// transposed+split weights per layer: [wq wk wv wao wi wfo], each [N][K] row-major
#define WQOFF  0
#define WKOFF  589824
#define WVOFF  1179648
#define WAOOFF 1769472
#define WIOFF  2359296
#define WFOOFF 4718592
#define LSTRIDE 7077888
__device__ __half g_wh[(size_t)NL*LSTRIDE];
__device__ __half g_wl[(size_t)NL*LSTRIDE];

// ---------------- PTX helpers ----------------
__device__ __forceinline__ uint32_t smem_u32(const void* p) {
    uint32_t a;
    asm("{ .reg .u64 t; cvta.to.shared.u64 t, %1; cvt.u32.u64 %0, t; }" : "=r"(a) : "l"(p));
    return a;
}
__device__ __forceinline__ void cpa16(uint32_t dst, const void* src) {
    asm volatile("cp.async.cg.shared.global [%0], [%1], 16;" :: "r"(dst), "l"(src));
}
#define CP_COMMIT() asm volatile("cp.async.commit_group;" ::: "memory")

__device__ __forceinline__ void ldsm4(uint32_t* r, uint32_t a) {
    asm volatile("ldmatrix.sync.aligned.m8n8.x4.shared.b16 {%0,%1,%2,%3}, [%4];"
        : "=r"(r[0]), "=r"(r[1]), "=r"(r[2]), "=r"(r[3]) : "r"(a));
}
__device__ __forceinline__ void ldsm4t(uint32_t* r, uint32_t a) {
    asm volatile("ldmatrix.sync.aligned.m8n8.x4.trans.shared.b16 {%0,%1,%2,%3}, [%4];"
        : "=r"(r[0]), "=r"(r[1]), "=r"(r[2]), "=r"(r[3]) : "r"(a));
}
// fp32-accum fp16 MMA
__device__ __forceinline__ void mma16816(float* c, const uint32_t* a, const uint32_t* b) {
    asm("mma.sync.aligned.m16n8k16.row.col.f32.f16.f16.f32 "
        "{%0,%1,%2,%3}, {%4,%5,%6,%7}, {%8,%9}, {%0,%1,%2,%3};"
        : "+f"(c[0]), "+f"(c[1]), "+f"(c[2]), "+f"(c[3])
        : "r"(a[0]), "r"(a[1]), "r"(a[2]), "r"(a[3]), "r"(b[0]), "r"(b[1]));
}
// fp16-accum fp16 MMA (for small correction products)
__device__ __forceinline__ void mma16816h(uint32_t* c, const uint32_t* a, const uint32_t* b) {
    asm("mma.sync.aligned.m16n8k16.row.col.f16.f16.f16.f16 "
        "{%0,%1}, {%2,%3,%4,%5}, {%6,%7}, {%0,%1};"
        : "+r"(c[0]), "+r"(c[1])
        : "r"(a[0]), "r"(a[1]), "r"(a[2]), "r"(a[3]), "r"(b[0]), "r"(b[1]));
}
__device__ __forceinline__ uint32_t pack_h2(__half a, __half b) {
    __half2 t = __halves2half2(a, b);
    return *(uint32_t*)&t;
}
__device__ __forceinline__ float2 h2f(uint32_t u) {
    __half2 h = *(__half2*)&u;
    return __half22float2(h);
}

// ---------------- fp16x3 HMMA GEMM: 128x128 tile, 512 threads, warp tile 32x32, K-chunk 64 ----
struct GemmArgs {
    const __half *ah, *al;
    const __half *bh0, *bh1, *bh2, *bl0, *bl1, *bl2;
    const float *bias0, *bias1, *bias2;
    const float *resid;
    float *c0, *c1, *c2;
    __half *ch0, *cl0, *ch1, *cl1, *ch2, *cl2;
    int K, N, gelu, outbf, Kld, ksplit;
};

#define ROWB 144               // 128B data + 16B pad
#define ABUF 18432             // 128 rows * 144B
#define STGB (4*ABUF)          // Ah, Al, Bh, Bl = 73728
#define NSTG 3
#define GEMM_SMEM (NSTG*STGB)  // 221184

__global__ __launch_bounds__(512) void gemm_tc(GemmArgs g) {
    extern __shared__ char smem[];
    const uint32_t su = smem_u32(smem);
    const int tid = threadIdx.x;
    const int lane = tid & 31, warp = tid >> 5;
    const int warpM = warp & 3, warpN = warp >> 2;
    const int m0 = blockIdx.y << 7, n0 = blockIdx.x << 7;

    const __half *bh, *bl; const float* bias; float* C;
    __half *CH, *CL;
    if (blockIdx.z == 0)      { bh=g.bh0; bl=g.bl0; bias=g.bias0; C=g.c0; CH=g.ch0; CL=g.cl0; }
    else if (blockIdx.z == 1) { bh=g.bh1; bl=g.bl1; bias=g.bias1; C=g.c1; CH=g.ch1; CL=g.cl1; }
    else                      { bh=g.bh2; bl=g.bl2; bias=g.bias2; C=g.c2; CH=g.ch2; CL=g.cl2; }
    const int K = g.K, N = g.N, nk = K >> 6;
    const int kbase = g.ksplit ? (int)blockIdx.z * K : 0;

    const int ldg_row = tid >> 3, ldg_c = tid & 7;
    const size_t ldab = (size_t)g.Kld * 2;
    const char* pAh = (const char*)g.ah + ((size_t)(m0 + ldg_row)) * ldab + (size_t)kbase*2 + ldg_c * 16;
    const char* pAl = (const char*)g.al + ((size_t)(m0 + ldg_row)) * ldab + (size_t)kbase*2 + ldg_c * 16;
    const char* pBh = (const char*)bh   + ((size_t)(n0 + ldg_row)) * ldab + (size_t)kbase*2 + ldg_c * 16;
    const char* pBl = (const char*)bl   + ((size_t)(n0 + ldg_row)) * ldab + (size_t)kbase*2 + ldg_c * 16;
    const size_t rowskip = 64 * ldab;
    const uint32_t sdst = ldg_row * ROWB + ldg_c * 16;

    auto load_chunk = [&](int j, int s) {
        uint32_t sb = su + s * STGB + sdst;
        size_t go = (size_t)j * 128;
        cpa16(sb,                        pAh + go);
        cpa16(sb + 64*ROWB,              pAh + rowskip + go);
        cpa16(sb +   ABUF,               pAl + go);
        cpa16(sb +   ABUF + 64*ROWB,     pAl + rowskip + go);
        cpa16(sb + 2*ABUF,               pBh + go);
        cpa16(sb + 2*ABUF + 64*ROWB,     pBh + rowskip + go);
        cpa16(sb + 3*ABUF,               pBl + go);
        cpa16(sb + 3*ABUF + 64*ROWB,     pBl + rowskip + go);
    };

    load_chunk(0, 0); CP_COMMIT();
    load_chunk(1, 1); CP_COMMIT();

    float acc[2][4][4];
    uint32_t facc[2][4][2];
    #pragma unroll
    for (int i = 0; i < 2; i++)
        #pragma unroll
        for (int j = 0; j < 4; j++) {
            #pragma unroll
            for (int r = 0; r < 4; r++) acc[i][j][r] = 0.f;
            facc[i][j][0] = 0u; facc[i][j][1] = 0u;
        }

    const uint32_t a_off = (uint32_t)(warpM*32 + (lane & 15)) * ROWB + (lane >> 4) * 16;
    const uint32_t b_off = (uint32_t)(warpN*32 + (((lane >> 4) & 1) << 3) + (lane & 7)) * ROWB
                         + ((lane >> 3) & 1) * 16;

    for (int i = 0; i < nk; i++) {
        asm volatile("cp.async.wait_group 1;" ::: "memory");
        __syncthreads();
        int j = i + 2;
        if (j < nk) load_chunk(j, j % NSTG);
        CP_COMMIT();

        uint32_t base = su + (i % NSTG) * STGB;
        #pragma unroll
        for (int ks = 0; ks < 4; ks++) {
            uint32_t ko = ks * 32;
            uint32_t ah0[4], ah1[4], al0[4], al1[4];
            uint32_t bhf0[4], bhf1[4], blf0[4], blf1[4];
            ldsm4(ah0, base + a_off + ko);
            ldsm4(ah1, base + a_off + 16*ROWB + ko);
            ldsm4(al0, base + ABUF + a_off + ko);
            ldsm4(al1, base + ABUF + a_off + 16*ROWB + ko);
            ldsm4(bhf0, base + 2*ABUF + b_off + ko);
            ldsm4(bhf1, base + 2*ABUF + b_off + 16*ROWB + ko);
            ldsm4(blf0, base + 3*ABUF + b_off + ko);
            ldsm4(blf1, base + 3*ABUF + b_off + 16*ROWB + ko);
            uint32_t* AH[2] = {ah0, ah1};
            uint32_t* AL[2] = {al0, al1};
            #pragma unroll
            for (int mt = 0; mt < 2; mt++) {
                // main product, fp32 accum
                mma16816(acc[mt][0], AH[mt], bhf0);
                mma16816(acc[mt][1], AH[mt], bhf0+2);
                mma16816(acc[mt][2], AH[mt], bhf1);
                mma16816(acc[mt][3], AH[mt], bhf1+2);
                // correction products, fp16 accum
                mma16816h(facc[mt][0], AH[mt], blf0);
                mma16816h(facc[mt][1], AH[mt], blf0+2);
                mma16816h(facc[mt][2], AH[mt], blf1);
                mma16816h(facc[mt][3], AH[mt], blf1+2);
                mma16816h(facc[mt][0], AL[mt], bhf0);
                mma16816h(facc[mt][1], AL[mt], bhf0+2);
                mma16816h(facc[mt][2], AL[mt], bhf1);
                mma16816h(facc[mt][3], AL[mt], bhf1+2);
            }
        }
    }

    const int erow = m0 + warpM*32 + (lane >> 2);
    const int ecol = n0 + warpN*32 + (lane & 3)*2;
    #pragma unroll
    for (int mt = 0; mt < 2; mt++) {
        #pragma unroll
        for (int nt = 0; nt < 4; nt++) {
            int c = ecol + nt*8;
            float b0 = bias ? bias[c] : 0.f, b1 = bias ? bias[c+1] : 0.f;
            float2 f0 = h2f(facc[mt][nt][0]);
            float2 f1 = h2f(facc[mt][nt][1]);
            #pragma unroll
            for (int half = 0; half < 2; half++) {
                int r = erow + mt*16 + half*8;
                float cx = half ? f1.x : f0.x;
                float cy = half ? f1.y : f0.y;
                float o0 = acc[mt][nt][half*2+0] + cx + b0;
                float o1 = acc[mt][nt][half*2+1] + cy + b1;
                if (g.resid) {
                    float2 rv = *(const float2*)(g.resid + (size_t)r * N + c);
                    o0 += rv.x; o1 += rv.y;
                }
                if (g.gelu) {
                    o0 = 0.5f * o0 * (1.0f + erff(o0 * 0.70710678118654752f));
                    o1 = 0.5f * o1 * (1.0f + erff(o1 * 0.70710678118654752f));
                }
                if (g.outbf) {
                    __half h0 = __float2half_rn(o0), h1 = __float2half_rn(o1);
                    __half l0 = __float2half_rn(o0 - __half2float(h0));
                    __half l1 = __float2half_rn(o1 - __half2float(h1));
                    *(uint32_t*)(CH + (size_t)r * N + c) = pack_h2(h0, h1);
                    *(uint32_t*)(CL + (size_t)r * N + c) = pack_h2(l0, l1);
                } else {
                    float2 ov; ov.x = o0; ov.y = o1;
                    *(float2*)(C + (size_t)r * N + c) = ov;
                }
            }
        }
    }
}

// ---------------- fused split-K reduce + LayerNorm (+ optional fp16 hi/lo out) ----------------
__global__ __launch_bounds__(256) void reduce_ln(
    const float* __restrict__ p0, const float* __restrict__ p1,
    const float* __restrict__ p2, const float* __restrict__ bias,
    const float* __restrict__ resid,
    const float* __restrict__ g, const float* __restrict__ b,
    float* __restrict__ out,
    __half* __restrict__ oh, __half* __restrict__ ol)
{
    const int row = blockIdx.x;
    const int tid = threadIdx.x;
    const size_t base = (size_t)row * HH;

    float v0, v1, v2;
    {
        int i0 = tid, i1 = tid + 256, i2 = tid + 512;
        v0 = p0[base+i0] + p1[base+i0] + p2[base+i0] + bias[i0] + resid[base+i0];
        v1 = p0[base+i1] + p1[base+i1] + p2[base+i1] + bias[i1] + resid[base+i1];
        v2 = p0[base+i2] + p1[base+i2] + p2[base+i2] + bias[i2] + resid[base+i2];
    }

    __shared__ float red[8];
    float s = v0 + v1 + v2;
    #pragma unroll
    for (int o2 = 16; o2; o2 >>= 1) s += __shfl_xor_sync(0xffffffffu, s, o2);
    if ((tid & 31) == 0) red[tid >> 5] = s;
    __syncthreads();
    float tot = 0.f;
    #pragma unroll
    for (int i = 0; i < 8; i++) tot += red[i];
    float mean = tot * (1.0f / 768.0f);

    float d0 = v0 - mean, d1 = v1 - mean, d2 = v2 - mean;
    float sq = d0*d0 + d1*d1 + d2*d2;
    __syncthreads();
    #pragma unroll
    for (int o2 = 16; o2; o2 >>= 1) sq += __shfl_xor_sync(0xffffffffu, sq, o2);
    if ((tid & 31) == 0) red[tid >> 5] = sq;
    __syncthreads();
    float tot2 = 0.f;
    #pragma unroll
    for (int i = 0; i < 8; i++) tot2 += red[i];
    float rstd = rsqrtf(tot2 * (1.0f / 768.0f) + 1e-12f);

    float r0 = d0 * rstd * g[tid]       + b[tid];
    float r1 = d1 * rstd * g[tid + 256] + b[tid + 256];
    float r2 = d2 * rstd * g[tid + 512] + b[tid + 512];
    out[base + tid] = r0; out[base + tid + 256] = r1; out[base + tid + 512] = r2;
    if (oh) {
        __half h0 = __float2half_rn(r0);
        __half h1 = __float2half_rn(r1);
        __half h2 = __float2half_rn(r2);
        oh[base + tid] = h0;       ol[base + tid]       = __float2half_rn(r0 - __half2float(h0));
        oh[base + tid + 256] = h1; ol[base + tid + 256] = __float2half_rn(r1 - __half2float(h1));
        oh[base + tid + 512] = h2; ol[base + tid + 512] = __float2half_rn(r2 - __half2float(h2));
    }
}

// ---------------- flash attention: K-tile 32, 3-stage pipeline, 3 CTAs/SM ----------------
#define QROW 144
#define FQBUF 9216            // 64*144
#define KROW 144
#define KSZ  4608             // 32*144
#define FSTG2 (4*KSZ)         // Kh, Kl, Vh, Vl = 18432
#define FNSTG 3
#define FSMEM (2*FQBUF + FNSTG*FSTG2)  // 73728

__global__ __launch_bounds__(128, 3) void flashattn(
    const __half* __restrict__ qh, const __half* __restrict__ ql,
    const __half* __restrict__ kh, const __half* __restrict__ kl,
    const __half* __restrict__ vh, const __half* __restrict__ vl,
    const __nv_bfloat16* __restrict__ madd,
    __half* __restrict__ cth, __half* __restrict__ ctl)
{
    extern __shared__ char smem[];
    const uint32_t su = smem_u32(smem);
    const int tid = threadIdx.x, lane = tid & 31, warp = tid >> 5;
    const int q0 = blockIdx.x * 64, bh = blockIdx.y;
    const int b = bh / NH, h = bh % NH;
    const int wr = warp * 16;

    const char* Qh = (const char*)(qh + ((size_t)b*SS + q0)*HH + h*DH);
    const char* Ql = (const char*)(ql + ((size_t)b*SS + q0)*HH + h*DH);
    const char* Kh = (const char*)(kh + ((size_t)b*SS)*HH + h*DH);
    const char* Kl = (const char*)(kl + ((size_t)b*SS)*HH + h*DH);
    const char* Vh = (const char*)(vh + ((size_t)b*SS)*HH + h*DH);
    const char* Vl = (const char*)(vl + ((size_t)b*SS)*HH + h*DH);

    #pragma unroll
    for (int c = 0; c < 4; c++) {
        int idx = tid + c*128;
        int row = idx >> 3, chn = idx & 7;
        uint32_t dst = su + row*QROW + chn*16;
        size_t so = (size_t)row*1536 + chn*16;
        cpa16(dst,         Qh + so);
        cpa16(dst + FQBUF, Ql + so);
    }
    CP_COMMIT();

    auto load_kv = [&](int j, int s) {
        uint32_t sb = su + 2*FQBUF + s*FSTG2;
        int k0 = j * 32;
        #pragma unroll
        for (int c = 0; c < 2; c++) {
            int idx = tid + c*128;
            int row = idx >> 3, chn = idx & 7;
            uint32_t dst = sb + row*KROW + chn*16;
            size_t ko = (size_t)(k0 + row)*1536 + chn*16;
            cpa16(dst,         Kh + ko);
            cpa16(dst +   KSZ, Kl + ko);
            cpa16(dst + 2*KSZ, Vh + ko);
            cpa16(dst + 3*KSZ, Vl + ko);
        }
    };
    load_kv(0, 0); CP_COMMIT();
    load_kv(1, 1); CP_COMMIT();

    asm volatile("cp.async.wait_group 2;" ::: "memory");
    __syncthreads();

    uint32_t qhf[4][4], qlf[4][4];
    {
        uint32_t abase = su + (uint32_t)(wr + (lane & 15))*QROW + (lane >> 4)*16;
        #pragma unroll
        for (int kc = 0; kc < 4; kc++) {
            ldsm4(qhf[kc], abase + kc*32);
            ldsm4(qlf[kc], abase + FQBUF + kc*32);
        }
    }

    float o[8][4];
    #pragma unroll
    for (int j = 0; j < 8; j++)
        #pragma unroll
        for (int r = 0; r < 4; r++) o[j][r] = 0.f;
    float m0 = -1e30f, m1 = -1e30f, l0 = 0.f, l1 = 0.f;

    const int r = lane >> 2;
    const int colb = (lane & 3) * 2;
    const __nv_bfloat16* mrow0 = madd + ((size_t)b*SS + (q0 + wr + r))*SS;
    const __nv_bfloat16* mrow8 = mrow0 + 8*SS;
    const uint32_t rowsel = (uint32_t)((((lane >> 4) & 1) << 3) + (lane & 7));
    const uint32_t bKoff = rowsel*KROW + ((lane >> 3) & 1)*16;
    const uint32_t bVoff = (uint32_t)(lane & 15)*KROW + ((lane >> 4) & 1)*16;

    for (int i = 0; i < 32; i++) {
        asm volatile("cp.async.wait_group 1;" ::: "memory");
        __syncthreads();
        if (i + 2 < 32) load_kv(i + 2, (i + 2) % 3);
        CP_COMMIT();

        const uint32_t sb = su + 2*FQBUF + (i % 3)*FSTG2;
        const int k0 = i * 32;

        // ---- S = Q K^T: main fp32-acc + corrections fp16-acc ----
        float sc_[4][4];
        uint32_t fsc[4][2];
        #pragma unroll
        for (int j = 0; j < 4; j++) {
            #pragma unroll
            for (int t = 0; t < 4; t++) sc_[j][t] = 0.f;
            fsc[j][0] = 0u; fsc[j][1] = 0u;
        }
        #pragma unroll
        for (int kc = 0; kc < 4; kc++) {
            uint32_t fh0[4], fl0[4], fh1[4], fl1[4];
            ldsm4(fh0, sb + bKoff + kc*32);
            ldsm4(fl0, sb + KSZ + bKoff + kc*32);
            ldsm4(fh1, sb + 16*KROW + bKoff + kc*32);
            ldsm4(fl1, sb + KSZ + 16*KROW + bKoff + kc*32);
            mma16816(sc_[0], qhf[kc], fh0);
            mma16816(sc_[1], qhf[kc], fh0+2);
            mma16816(sc_[2], qhf[kc], fh1);
            mma16816(sc_[3], qhf[kc], fh1+2);
            mma16816h(fsc[0], qhf[kc], fl0);
            mma16816h(fsc[1], qhf[kc], fl0+2);
            mma16816h(fsc[2], qhf[kc], fl1);
            mma16816h(fsc[3], qhf[kc], fl1+2);
            mma16816h(fsc[0], qlf[kc], fh0);
            mma16816h(fsc[1], qlf[kc], fh0+2);
            mma16816h(fsc[2], qlf[kc], fh1);
            mma16816h(fsc[3], qlf[kc], fh1+2);
        }
        // fold corrections + mask + scale
        #pragma unroll
        for (int j = 0; j < 4; j++) {
            float2 f0 = h2f(fsc[j][0]);
            float2 f1 = h2f(fsc[j][1]);
            int kc2 = k0 + j*8 + colb;
            __nv_bfloat162 ma = *(const __nv_bfloat162*)(mrow0 + kc2);
            __nv_bfloat162 mb = *(const __nv_bfloat162*)(mrow8 + kc2);
            float2 fa = __bfloat1622float2(ma);
            float2 fb = __bfloat1622float2(mb);
            sc_[j][0] = (sc_[j][0] + f0.x)*0.125f + fa.x;
            sc_[j][1] = (sc_[j][1] + f0.y)*0.125f + fa.y;
            sc_[j][2] = (sc_[j][2] + f1.x)*0.125f + fb.x;
            sc_[j][3] = (sc_[j][3] + f1.y)*0.125f + fb.y;
        }
        // ---- online softmax ----
        float mx0 = -1e30f, mx1 = -1e30f;
        #pragma unroll
        for (int j = 0; j < 4; j++) {
            mx0 = fmaxf(mx0, fmaxf(sc_[j][0], sc_[j][1]));
            mx1 = fmaxf(mx1, fmaxf(sc_[j][2], sc_[j][3]));
        }
        mx0 = fmaxf(mx0, __shfl_xor_sync(0xffffffffu, mx0, 1));
        mx0 = fmaxf(mx0, __shfl_xor_sync(0xffffffffu, mx0, 2));
        mx1 = fmaxf(mx1, __shfl_xor_sync(0xffffffffu, mx1, 1));
        mx1 = fmaxf(mx1, __shfl_xor_sync(0xffffffffu, mx1, 2));
        float mn0 = fmaxf(m0, mx0), mn1 = fmaxf(m1, mx1);
        float sf0 = __expf(m0 - mn0), sf1 = __expf(m1 - mn1);
        m0 = mn0; m1 = mn1;
        float rs0 = 0.f, rs1 = 0.f;
        #pragma unroll
        for (int j = 0; j < 4; j++) {
            sc_[j][0] = __expf(sc_[j][0] - mn0);
            sc_[j][1] = __expf(sc_[j][1] - mn0);
            sc_[j][2] = __expf(sc_[j][2] - mn1);
            sc_[j][3] = __expf(sc_[j][3] - mn1);
            rs0 += sc_[j][0] + sc_[j][1];
            rs1 += sc_[j][2] + sc_[j][3];
        }
        rs0 += __shfl_xor_sync(0xffffffffu, rs0, 1);
        rs0 += __shfl_xor_sync(0xffffffffu, rs0, 2);
        rs1 += __shfl_xor_sync(0xffffffffu, rs1, 1);
        rs1 += __shfl_xor_sync(0xffffffffu, rs1, 2);
        l0 = l0*sf0 + rs0;
        l1 = l1*sf1 + rs1;
        #pragma unroll
        for (int j = 0; j < 8; j++) {
            o[j][0] *= sf0; o[j][1] *= sf0; o[j][2] *= sf1; o[j][3] *= sf1;
        }
        // ---- P -> fp16 hi/lo A-fragments ----
        uint32_t phf[2][4], plf[2][4];
        #pragma unroll
        for (int kc = 0; kc < 2; kc++) {
            #pragma unroll
            for (int half = 0; half < 2; half++) {
                int j = 2*kc + half;
                __half h0 = __float2half_rn(sc_[j][0]);
                __half h1 = __float2half_rn(sc_[j][1]);
                __half h2 = __float2half_rn(sc_[j][2]);
                __half h3 = __float2half_rn(sc_[j][3]);
                phf[kc][half*2+0] = pack_h2(h0, h1);
                phf[kc][half*2+1] = pack_h2(h2, h3);
                plf[kc][half*2+0] = pack_h2(
                    __float2half_rn(sc_[j][0] - __half2float(h0)),
                    __float2half_rn(sc_[j][1] - __half2float(h1)));
                plf[kc][half*2+1] = pack_h2(
                    __float2half_rn(sc_[j][2] - __half2float(h2)),
                    __float2half_rn(sc_[j][3] - __half2float(h3)));
            }
        }
        // ---- O += P V: main fp32-acc + corrections fp16-acc (per-iter fold) ----
        uint32_t of16[8][2];
        #pragma unroll
        for (int j = 0; j < 8; j++) { of16[j][0] = 0u; of16[j][1] = 0u; }
        #pragma unroll
        for (int kc = 0; kc < 2; kc++) {
            #pragma unroll
            for (int ntp = 0; ntp < 4; ntp += 2) {
                uint32_t fha[4], fla[4], fhb[4], flb[4];
                ldsm4t(fha, sb + 2*KSZ + kc*16*KROW + bVoff + ntp*32);
                ldsm4t(fla, sb + 3*KSZ + kc*16*KROW + bVoff + ntp*32);
                ldsm4t(fhb, sb + 2*KSZ + kc*16*KROW + bVoff + (ntp+1)*32);
                ldsm4t(flb, sb + 3*KSZ + kc*16*KROW + bVoff + (ntp+1)*32);
                mma16816(o[2*ntp],   phf[kc], fha);
                mma16816(o[2*ntp+1], phf[kc], fha+2);
                mma16816(o[2*ntp+2], phf[kc], fhb);
                mma16816(o[2*ntp+3], phf[kc], fhb+2);
                mma16816h(of16[2*ntp],   phf[kc], fla);
                mma16816h(of16[2*ntp+1], phf[kc], fla+2);
                mma16816h(of16[2*ntp+2], phf[kc], flb);
                mma16816h(of16[2*ntp+3], phf[kc], flb+2);
                mma16816h(of16[2*ntp],   plf[kc], fha);
                mma16816h(of16[2*ntp+1], plf[kc], fha+2);
                mma16816h(of16[2*ntp+2], plf[kc], fhb);
                mma16816h(of16[2*ntp+3], plf[kc], fhb+2);
            }
        }
        #pragma unroll
        for (int j = 0; j < 8; j++) {
            float2 a = h2f(of16[j][0]);
            float2 c = h2f(of16[j][1]);
            o[j][0] += a.x; o[j][1] += a.y; o[j][2] += c.x; o[j][3] += c.y;
        }
    }

    float inv0 = 1.f / l0, inv1 = 1.f / l1;
    size_t base0 = ((size_t)b*SS + (q0 + wr + r))*HH + h*DH;
    size_t base8 = base0 + (size_t)8*HH;
    #pragma unroll
    for (int j = 0; j < 8; j++) {
        int col = j*8 + colb;
        float a0 = o[j][0]*inv0, a1 = o[j][1]*inv0;
        float a2 = o[j][2]*inv1, a3 = o[j][3]*inv1;
        __half h0 = __float2half_rn(a0), h1 = __float2half_rn(a1);
        __half h2 = __float2half_rn(a2), h3 = __float2half_rn(a3);
        *(uint32_t*)(cth + base0 + col) = pack_h2(h0, h1);
        *(uint32_t*)(ctl + base0 + col) = pack_h2(
            __float2half_rn(a0 - __half2float(h0)),
            __float2half_rn(a1 - __half2float(h1)));
        *(uint32_t*)(cth + base8 + col) = pack_h2(h2, h3);
        *(uint32_t*)(ctl + base8 + col) = pack_h2(
            __float2half_rn(a2 - __half2float(h2)),
            __float2half_rn(a3 - __half2float(h3)));
    }
}

// ---------------- mask -> bf16 additive prebake ----------------
__global__ __launch_bounds__(256) void maskprep(const int* __restrict__ mask,
                                                __nv_bfloat16* __restrict__ madd, int n4)
{
    int i = blockIdx.x * 256 + threadIdx.x;
    if (i >= n4) return;
    int4 m = ((const int4*)mask)[i];
    __nv_bfloat16 z = __float2bfloat16(0.f), neg = __float2bfloat16(-10000.f);
    __nv_bfloat162 a = __halves2bfloat162(m.x ? z : neg, m.y ? z : neg);
    __nv_bfloat162 b = __halves2bfloat162(m.z ? z : neg, m.w ? z : neg);
    uint2 o;
    o.x = *(uint32_t*)&a; o.y = *(uint32_t*)&b;
    *(uint2*)(madd + (size_t)i*4) = o;
}

// ---------------- split fp32 -> fp16 hi/lo (only for initial x) ----------------
__global__ __launch_bounds__(256) void split_kernel(const float* __restrict__ x,
    __half* __restrict__ hi, __half* __restrict__ lo, int n4)
{
    int i = blockIdx.x * 256 + threadIdx.x;
    if (i >= n4) return;
    float4 v = ((const float4*)x)[i];
    __half h0 = __float2half_rn(v.x), h1 = __float2half_rn(v.y);
    __half h2 = __float2half_rn(v.z), h3 = __float2half_rn(v.w);
    uint2 H, L;
    H.x = pack_h2(h0, h1); H.y = pack_h2(h2, h3);
    L.x = pack_h2(__float2half_rn(v.x - __half2float(h0)),
                  __float2half_rn(v.y - __half2float(h1)));
    L.y = pack_h2(__float2half_rn(v.z - __half2float(h2)),
                  __float2half_rn(v.w - __half2float(h3)));
    *(uint2*)(hi + (size_t)i*4) = H;
    *(uint2*)(lo + (size_t)i*4) = L;
}

// ---------------- batched weight transpose + split ----------------
__global__ __launch_bounds__(256) void wtrans_all(
    const float* __restrict__ Wq, const float* __restrict__ Wk,
    const float* __restrict__ Wv, const float* __restrict__ Wao,
    const float* __restrict__ Wi, const float* __restrict__ Wfo,
    __half* __restrict__ wh, __half* __restrict__ wl)
{
    __shared__ float t[64][33];
    const int tid = threadIdx.x;
    const int l = blockIdx.z;
    int x = blockIdx.x;

    const float* W; int K_, N_; size_t off;
    if (x < 1152) {
        int m = x / 288; x -= m * 288;
        K_ = HH; N_ = HH;
        W = (m == 0 ? Wq : m == 1 ? Wk : m == 2 ? Wv : Wao) + (size_t)l * HH * HH;
        off = (m == 0 ? WQOFF : m == 1 ? WKOFF : m == 2 ? WVOFF : WAOOFF);
    } else if (x < 2304) {
        x -= 1152; K_ = HH; N_ = FF;
        W = Wi + (size_t)l * HH * FF; off = WIOFF;
    } else {
        x -= 2304; K_ = FF; N_ = HH;
        W = Wfo + (size_t)l * FF * HH; off = WFOOFF;
    }
    const int ntn = N_ >> 5;
    const int k0 = (x / ntn) << 6, n0 = (x % ntn) << 5;

    {
        int r = tid >> 5, c = tid & 31;
        #pragma unroll
        for (int i = 0; i < 8; i++)
            t[r + i*8][c] = W[(size_t)(k0 + r + i*8) * N_ + n0 + c];
    }
    __syncthreads();

    __half* hi = wh + (size_t)l * LSTRIDE + off;
    __half* lo = wl + (size_t)l * LSTRIDE + off;
    #pragma unroll
    for (int it = 0; it < 2; it++) {
        int idx = tid + it * 256;
        int nl = idx >> 4, kq = idx & 15;
        float v0 = t[kq*4+0][nl], v1 = t[kq*4+1][nl];
        float v2 = t[kq*4+2][nl], v3 = t[kq*4+3][nl];
        __half h0 = __float2half_rn(v0), h1 = __float2half_rn(v1);
        __half h2 = __float2half_rn(v2), h3 = __float2half_rn(v3);
        uint2 hv, lv;
        hv.x = pack_h2(h0, h1); hv.y = pack_h2(h2, h3);
        lv.x = pack_h2(__float2half_rn(v0 - __half2float(h0)),
                       __float2half_rn(v1 - __half2float(h1)));
        lv.y = pack_h2(__float2half_rn(v2 - __half2float(h2)),
                       __float2half_rn(v3 - __half2float(h3)));
        size_t base = (size_t)(n0 + nl) * K_ + k0 + kq*4;
        *(uint2*)(hi + base) = hv;
        *(uint2*)(lo + base) = lv;
    }
}

// ---------------- launch ----------------
extern "C" void kernel_launch(void* const* d_in, const int* in_sizes, int n_in,
                              void* d_out, int out_size)
{
    const float* x    = (const float*)d_in[0];
    const int*   mask = (const int*)  d_in[1];
    const float* Wq   = (const float*)d_in[2];
    const float* bq   = (const float*)d_in[3];
    const float* Wk   = (const float*)d_in[4];
    const float* bk   = (const float*)d_in[5];
    const float* Wv   = (const float*)d_in[6];
    const float* bv   = (const float*)d_in[7];
    const float* Wao  = (const float*)d_in[8];
    const float* bao  = (const float*)d_in[9];
    const float* g1   = (const float*)d_in[10];
    const float* b1   = (const float*)d_in[11];
    const float* Wi   = (const float*)d_in[12];
    const float* bi   = (const float*)d_in[13];
    const float* Wfo  = (const float*)d_in[14];
    const float* bfo  = (const float*)d_in[15];
    const float* g2   = (const float*)d_in[16];
    const float* b2   = (const float*)d_in[17];

    float *h_, *attn_, *p0_, *p1_, *p2_;
    __half *hh_, *hl_, *qh_, *ql_, *kh_, *kl_, *vh_, *vl_;
    __half *cth_, *ctl_, *aah_, *aal_, *ih_, *il_, *wh_, *wl_;
    __nv_bfloat16 *madd_;
    cudaGetSymbolAddress((void**)&h_,    g_h);
    cudaGetSymbolAddress((void**)&attn_, g_attn);
    cudaGetSymbolAddress((void**)&p0_,   g_p0);
    cudaGetSymbolAddress((void**)&p1_,   g_p1);
    cudaGetSymbolAddress((void**)&p2_,   g_p2);
    cudaGetSymbolAddress((void**)&hh_,   g_hh);
    cudaGetSymbolAddress((void**)&hl_,   g_hl);
    cudaGetSymbolAddress((void**)&qh_,   g_qh);
    cudaGetSymbolAddress((void**)&ql_,   g_ql);
    cudaGetSymbolAddress((void**)&kh_,   g_kh);
    cudaGetSymbolAddress((void**)&kl_,   g_kl);
    cudaGetSymbolAddress((void**)&vh_,   g_vh);
    cudaGetSymbolAddress((void**)&vl_,   g_vl);
    cudaGetSymbolAddress((void**)&cth_,  g_cth);
    cudaGetSymbolAddress((void**)&ctl_,  g_ctl);
    cudaGetSymbolAddress((void**)&aah_,  g_aah);
    cudaGetSymbolAddress((void**)&aal_,  g_aal);
    cudaGetSymbolAddress((void**)&ih_,   g_ih);
    cudaGetSymbolAddress((void**)&il_,   g_il);
    cudaGetSymbolAddress((void**)&wh_,   g_wh);
    cudaGetSymbolAddress((void**)&wl_,   g_wl);
    cudaGetSymbolAddress((void**)&madd_, g_madd);

    cudaFuncSetAttribute(gemm_tc,
                         cudaFuncAttributeMaxDynamicSharedMemorySize, GEMM_SMEM);
    cudaFuncSetAttribute(flashattn,
                         cudaFuncAttributeMaxDynamicSharedMemorySize, FSMEM);

    const int M = BB * SS;  // 2048
    const int n4 = M * HH / 4;
    const int mn4 = BB * SS * SS / 4;

    wtrans_all<<<dim3(3456, 1, NL), 256>>>(Wq, Wk, Wv, Wao, Wi, Wfo, wh_, wl_);
    maskprep<<<(mn4 + 255)/256, 256>>>(mask, madd_, mn4);
    split_kernel<<<(n4 + 255)/256, 256>>>(x, hh_, hl_, n4);

    for (int l = 0; l < NL; l++) {
        const float* hin = (l == 0) ? x : h_;
        size_t lo = (size_t)l * LSTRIDE;

        // QKV -> fp16 hi/lo outputs
        {
            GemmArgs a = {};
            a.ah = hh_; a.al = hl_;
            a.bh0 = wh_+lo+WQOFF; a.bh1 = wh_+lo+WKOFF; a.bh2 = wh_+lo+WVOFF;
            a.bl0 = wl_+lo+WQOFF; a.bl1 = wl_+lo+WKOFF; a.bl2 = wl_+lo+WVOFF;
            a.bias0 = bq + l*HH; a.bias1 = bk + l*HH; a.bias2 = bv + l*HH;
            a.ch0 = qh_; a.cl0 = ql_; a.ch1 = kh_; a.cl1 = kl_; a.ch2 = vh_; a.cl2 = vl_;
            a.K = HH; a.N = HH; a.gelu = 0; a.outbf = 1; a.Kld = HH; a.ksplit = 0;
            gemm_tc<<<dim3(HH/128, M/128, 3), 512, GEMM_SMEM>>>(a);
        }

        flashattn<<<dim3(SS/64, BB*NH), 128, FSMEM>>>(qh_, ql_, kh_, kl_, vh_, vl_,
                                                      madd_, cth_, ctl_);

        // AO proj: split-K=3 -> partials -> fused reduce+LN
        {
            GemmArgs a = {};
            a.ah = cth_; a.al = ctl_;
            a.bh0 = wh_+lo+WAOOFF; a.bh1 = a.bh0; a.bh2 = a.bh0;
            a.bl0 = wl_+lo+WAOOFF; a.bl1 = a.bl0; a.bl2 = a.bl0;
            a.c0 = p0_; a.c1 = p1_; a.c2 = p2_;
            a.K = 256; a.N = HH; a.gelu = 0; a.outbf = 0; a.Kld = HH; a.ksplit = 1;
            gemm_tc<<<dim3(HH/128, M/128, 3), 512, GEMM_SMEM>>>(a);
        }
        reduce_ln<<<M, 256>>>(p0_, p1_, p2_, bao + l*HH, hin,
                              g1 + l*HH, b1 + l*HH, attn_, aah_, aal_);

        // FFN1 (gelu) -> fp16 hi/lo
        {
            GemmArgs a = {};
            a.ah = aah_; a.al = aal_;
            a.bh0 = wh_+lo+WIOFF; a.bh1 = a.bh0; a.bh2 = a.bh0;
            a.bl0 = wl_+lo+WIOFF; a.bl1 = a.bl0; a.bl2 = a.bl0;
            a.bias0 = bi + l*FF; a.bias1 = a.bias0; a.bias2 = a.bias0;
            a.ch0 = ih_; a.cl0 = il_; a.ch1 = ih_; a.cl1 = il_; a.ch2 = ih_; a.cl2 = il_;
            a.K = HH; a.N = FF; a.gelu = 1; a.outbf = 1; a.Kld = HH; a.ksplit = 0;
            gemm_tc<<<dim3(FF/128, M/128, 1), 512, GEMM_SMEM>>>(a);
        }

        // FFN2: split-K=3 -> partials -> fused reduce+LN
        {
            GemmArgs a = {};
            a.ah = ih_; a.al = il_;
            a.bh0 = wh_+lo+WFOOFF; a.bh1 = a.bh0; a.bh2 = a.bh0;
            a.bl0 = wl_+lo+WFOOFF; a.bl1 = a.bl0; a.bl2 = a.bl0;
            a.c0 = p0_; a.c1 = p1_; a.c2 = p2_;
            a.K = 1024; a.N = HH; a.gelu = 0; a.outbf = 0; a.Kld = FF; a.ksplit = 1;
            gemm_tc<<<dim3(HH/128, M/128, 3), 512, GEMM_SMEM>>>(a);
        }
        if (l == NL - 1) {
            reduce_ln<<<M, 256>>>(p0_, p1_, p2_, bfo + l*HH, attn_,
                                  g2 + l*HH, b2 + l*HH, (float*)d_out,
                                  (__half*)nullptr, (__half*)nullptr);
        } else {
            reduce_ln<<<M, 256>>>(p0_, p1_, p2_, bfo + l*HH, attn_,
                                  g2 + l*HH, b2 + l*HH, h_, hh_, hl_);
        }
    }
}

// round 14
// speedup vs baseline: 1.2368x; 1.2368x over previous
#include <cuda_runtime.h>
#include <cuda_bf16.h>
#include <cuda_fp16.h>
#include <math.h>
#include <stdint.h>

#define BB 2
#define SS 1024
#define HH 768
#define NH 12
#define DH 64
#define FF 3072
#define NL 4

// ---------------- scratch (device globals; no allocation allowed) ----------------
__device__ float g_h[BB*SS*HH];
__device__ float g_attn[BB*SS*HH];
__device__ float g_p0[BB*SS*HH];
__device__ float g_p1[BB*SS*HH];
__device__ float g_p2[BB*SS*HH];

__device__ __half g_hh[BB*SS*HH], g_hl[BB*SS*HH];
__device__ __half g_qh[BB*SS*HH], g_ql[BB*SS*HH];
__device__ __half g_kh[BB*SS*HH], g_kl[BB*SS*HH];
__device__ __half g_vh[BB*SS*HH], g_vl[BB*SS*HH];
__device__ __half g_cth[BB*SS*HH], g_ctl[BB*SS*HH];
__device__ __half g_aah[BB*SS*HH], g_aal[BB*SS*HH];
__device__ __half g_ih[BB*SS*FF], g_il[BB*SS*FF];
__device__ __nv_bfloat16 g_madd[(size_t)BB*SS*SS];   // (1-mask)*-10000 as bf16

// transposed weights per layer (single fp16): [wq wk wv wao wi wfo], each [N][K] row-major
#define WQOFF  0
#define WKOFF  589824
#define WVOFF  1179648
#define WAOOFF 1769472
#define WIOFF  2359296
#define WFOOFF 4718592
#define LSTRIDE 7077888
__device__ __half g_wh[(size_t)NL*LSTRIDE];

// ---------------- PTX helpers ----------------
__device__ __forceinline__ uint32_t smem_u32(const void* p) {
    uint32_t a;
    asm("{ .reg .u64 t; cvta.to.shared.u64 t, %1; cvt.u32.u64 %0, t; }" : "=r"(a) : "l"(p));
    return a;
}
__device__ __forceinline__ void cpa16(uint32_t dst, const void* src) {
    asm volatile("cp.async.cg.shared.global [%0], [%1], 16;" :: "r"(dst), "l"(src));
}
#define CP_COMMIT() asm volatile("cp.async.commit_group;" ::: "memory")

__device__ __forceinline__ void ldsm4(uint32_t* r, uint32_t a) {
    asm volatile("ldmatrix.sync.aligned.m8n8.x4.shared.b16 {%0,%1,%2,%3}, [%4];"
        : "=r"(r[0]), "=r"(r[1]), "=r"(r[2]), "=r"(r[3]) : "r"(a));
}
__device__ __forceinline__ void ldsm4t(uint32_t* r, uint32_t a) {
    asm volatile("ldmatrix.sync.aligned.m8n8.x4.trans.shared.b16 {%0,%1,%2,%3}, [%4];"
        : "=r"(r[0]), "=r"(r[1]), "=r"(r[2]), "=r"(r[3]) : "r"(a));
}
__device__ __forceinline__ void mma16816(float* c, const uint32_t* a, const uint32_t* b) {
    asm("mma.sync.aligned.m16n8k16.row.col.f32.f16.f16.f32 "
        "{%0,%1,%2,%3}, {%4,%5,%6,%7}, {%8,%9}, {%0,%1,%2,%3};"
        : "+f"(c[0]), "+f"(c[1]), "+f"(c[2]), "+f"(c[3])
        : "r"(a[0]), "r"(a[1]), "r"(a[2]), "r"(a[3]), "r"(b[0]), "r"(b[1]));
}
__device__ __forceinline__ uint32_t pack_h2(__half a, __half b) {
    __half2 t = __halves2half2(a, b);
    return *(uint32_t*)&t;
}

// ---------------- fp16 x2 GEMM: C = (Ah+Al) @ W16^T; 128x128 tile, 512 thr, K-chunk 64 ----
struct GemmArgs {
    const __half *ah, *al;
    const __half *bh0, *bh1, *bh2;
    const float *bias0, *bias1, *bias2;
    const float *resid;
    float *c0, *c1, *c2;
    __half *ch0, *cl0, *ch1, *cl1, *ch2, *cl2;
    int K, N, gelu, outbf, Kld, ksplit;
};

#define ROWB 144               // 128B data + 16B pad
#define ABUF 18432             // 128 rows * 144B
#define STGB (3*ABUF)          // Ah, Al, Bh = 55296
#define NSTG 3
#define GEMM_SMEM (NSTG*STGB)  // 165888

__global__ __launch_bounds__(512) void gemm_tc(GemmArgs g) {
    extern __shared__ char smem[];
    const uint32_t su = smem_u32(smem);
    const int tid = threadIdx.x;
    const int lane = tid & 31, warp = tid >> 5;
    const int warpM = warp & 3, warpN = warp >> 2;
    const int m0 = blockIdx.y << 7, n0 = blockIdx.x << 7;

    const __half *bh; const float* bias; float* C;
    __half *CH, *CL;
    if (blockIdx.z == 0)      { bh=g.bh0; bias=g.bias0; C=g.c0; CH=g.ch0; CL=g.cl0; }
    else if (blockIdx.z == 1) { bh=g.bh1; bias=g.bias1; C=g.c1; CH=g.ch1; CL=g.cl1; }
    else                      { bh=g.bh2; bias=g.bias2; C=g.c2; CH=g.ch2; CL=g.cl2; }
    const int K = g.K, N = g.N, nk = K >> 6;
    const int kbase = g.ksplit ? (int)blockIdx.z * K : 0;

    const int ldg_row = tid >> 3, ldg_c = tid & 7;
    const size_t ldab = (size_t)g.Kld * 2;
    const char* pAh = (const char*)g.ah + ((size_t)(m0 + ldg_row)) * ldab + (size_t)kbase*2 + ldg_c * 16;
    const char* pAl = (const char*)g.al + ((size_t)(m0 + ldg_row)) * ldab + (size_t)kbase*2 + ldg_c * 16;
    const char* pBh = (const char*)bh   + ((size_t)(n0 + ldg_row)) * ldab + (size_t)kbase*2 + ldg_c * 16;
    const size_t rowskip = 64 * ldab;
    const uint32_t sdst = ldg_row * ROWB + ldg_c * 16;

    auto load_chunk = [&](int j, int s) {
        uint32_t sb = su + s * STGB + sdst;
        size_t go = (size_t)j * 128;
        cpa16(sb,                        pAh + go);
        cpa16(sb + 64*ROWB,              pAh + rowskip + go);
        cpa16(sb +   ABUF,               pAl + go);
        cpa16(sb +   ABUF + 64*ROWB,     pAl + rowskip + go);
        cpa16(sb + 2*ABUF,               pBh + go);
        cpa16(sb + 2*ABUF + 64*ROWB,     pBh + rowskip + go);
    };

    load_chunk(0, 0); CP_COMMIT();
    load_chunk(1, 1); CP_COMMIT();

    float acc[2][4][4];
    #pragma unroll
    for (int i = 0; i < 2; i++)
        #pragma unroll
        for (int j = 0; j < 4; j++)
            #pragma unroll
            for (int r = 0; r < 4; r++) acc[i][j][r] = 0.f;

    const uint32_t a_off = (uint32_t)(warpM*32 + (lane & 15)) * ROWB + (lane >> 4) * 16;
    const uint32_t b_off = (uint32_t)(warpN*32 + (((lane >> 4) & 1) << 3) + (lane & 7)) * ROWB
                         + ((lane >> 3) & 1) * 16;

    for (int i = 0; i < nk; i++) {
        asm volatile("cp.async.wait_group 1;" ::: "memory");
        __syncthreads();
        int j = i + 2;
        if (j < nk) load_chunk(j, j % NSTG);
        CP_COMMIT();

        uint32_t base = su + (i % NSTG) * STGB;
        #pragma unroll
        for (int ks = 0; ks < 4; ks++) {
            uint32_t ko = ks * 32;
            uint32_t ah0[4], ah1[4], al0[4], al1[4];
            uint32_t bhf0[4], bhf1[4];
            ldsm4(ah0, base + a_off + ko);
            ldsm4(ah1, base + a_off + 16*ROWB + ko);
            ldsm4(al0, base + ABUF + a_off + ko);
            ldsm4(al1, base + ABUF + a_off + 16*ROWB + ko);
            ldsm4(bhf0, base + 2*ABUF + b_off + ko);
            ldsm4(bhf1, base + 2*ABUF + b_off + 16*ROWB + ko);
            uint32_t* AH[2] = {ah0, ah1};
            uint32_t* AL[2] = {al0, al1};
            #pragma unroll
            for (int mt = 0; mt < 2; mt++) {
                mma16816(acc[mt][0], AH[mt], bhf0);
                mma16816(acc[mt][1], AH[mt], bhf0+2);
                mma16816(acc[mt][2], AH[mt], bhf1);
                mma16816(acc[mt][3], AH[mt], bhf1+2);
                mma16816(acc[mt][0], AL[mt], bhf0);
                mma16816(acc[mt][1], AL[mt], bhf0+2);
                mma16816(acc[mt][2], AL[mt], bhf1);
                mma16816(acc[mt][3], AL[mt], bhf1+2);
            }
        }
    }

    const int erow = m0 + warpM*32 + (lane >> 2);
    const int ecol = n0 + warpN*32 + (lane & 3)*2;
    #pragma unroll
    for (int mt = 0; mt < 2; mt++) {
        #pragma unroll
        for (int nt = 0; nt < 4; nt++) {
            int c = ecol + nt*8;
            float b0 = bias ? bias[c] : 0.f, b1 = bias ? bias[c+1] : 0.f;
            #pragma unroll
            for (int half = 0; half < 2; half++) {
                int r = erow + mt*16 + half*8;
                float o0 = acc[mt][nt][half*2+0] + b0;
                float o1 = acc[mt][nt][half*2+1] + b1;
                if (g.resid) {
                    float2 rv = *(const float2*)(g.resid + (size_t)r * N + c);
                    o0 += rv.x; o1 += rv.y;
                }
                if (g.gelu) {
                    o0 = 0.5f * o0 * (1.0f + erff(o0 * 0.70710678118654752f));
                    o1 = 0.5f * o1 * (1.0f + erff(o1 * 0.70710678118654752f));
                }
                if (g.outbf) {
                    __half h0 = __float2half_rn(o0), h1 = __float2half_rn(o1);
                    __half l0 = __float2half_rn(o0 - __half2float(h0));
                    __half l1 = __float2half_rn(o1 - __half2float(h1));
                    *(uint32_t*)(CH + (size_t)r * N + c) = pack_h2(h0, h1);
                    *(uint32_t*)(CL + (size_t)r * N + c) = pack_h2(l0, l1);
                } else {
                    float2 ov; ov.x = o0; ov.y = o1;
                    *(float2*)(C + (size_t)r * N + c) = ov;
                }
            }
        }
    }
}

// ---------------- fused split-K reduce + LayerNorm (+ optional fp16 hi/lo out) ----------------
__global__ __launch_bounds__(256) void reduce_ln(
    const float* __restrict__ p0, const float* __restrict__ p1,
    const float* __restrict__ p2, const float* __restrict__ bias,
    const float* __restrict__ resid,
    const float* __restrict__ g, const float* __restrict__ b,
    float* __restrict__ out,
    __half* __restrict__ oh, __half* __restrict__ ol)
{
    const int row = blockIdx.x;
    const int tid = threadIdx.x;
    const size_t base = (size_t)row * HH;

    float v0, v1, v2;
    {
        int i0 = tid, i1 = tid + 256, i2 = tid + 512;
        v0 = p0[base+i0] + p1[base+i0] + p2[base+i0] + bias[i0] + resid[base+i0];
        v1 = p0[base+i1] + p1[base+i1] + p2[base+i1] + bias[i1] + resid[base+i1];
        v2 = p0[base+i2] + p1[base+i2] + p2[base+i2] + bias[i2] + resid[base+i2];
    }

    __shared__ float red[8];
    float s = v0 + v1 + v2;
    #pragma unroll
    for (int o2 = 16; o2; o2 >>= 1) s += __shfl_xor_sync(0xffffffffu, s, o2);
    if ((tid & 31) == 0) red[tid >> 5] = s;
    __syncthreads();
    float tot = 0.f;
    #pragma unroll
    for (int i = 0; i < 8; i++) tot += red[i];
    float mean = tot * (1.0f / 768.0f);

    float d0 = v0 - mean, d1 = v1 - mean, d2 = v2 - mean;
    float sq = d0*d0 + d1*d1 + d2*d2;
    __syncthreads();
    #pragma unroll
    for (int o2 = 16; o2; o2 >>= 1) sq += __shfl_xor_sync(0xffffffffu, sq, o2);
    if ((tid & 31) == 0) red[tid >> 5] = sq;
    __syncthreads();
    float tot2 = 0.f;
    #pragma unroll
    for (int i = 0; i < 8; i++) tot2 += red[i];
    float rstd = rsqrtf(tot2 * (1.0f / 768.0f) + 1e-12f);

    float r0 = d0 * rstd * g[tid]       + b[tid];
    float r1 = d1 * rstd * g[tid + 256] + b[tid + 256];
    float r2 = d2 * rstd * g[tid + 512] + b[tid + 512];
    out[base + tid] = r0; out[base + tid + 256] = r1; out[base + tid + 512] = r2;
    if (oh) {
        __half h0 = __float2half_rn(r0);
        __half h1 = __float2half_rn(r1);
        __half h2 = __float2half_rn(r2);
        oh[base + tid] = h0;       ol[base + tid]       = __float2half_rn(r0 - __half2float(h0));
        oh[base + tid + 256] = h1; ol[base + tid + 256] = __float2half_rn(r1 - __half2float(h1));
        oh[base + tid + 512] = h2; ol[base + tid + 512] = __float2half_rn(r2 - __half2float(h2));
    }
}

// ---------------- flash attention (full x3, fp32 accum): K-tile 32, 3 stages, 3 CTAs/SM ----
#define QROW 144
#define FQBUF 9216            // 64*144
#define KROW 144
#define KSZ  4608             // 32*144
#define FSTG2 (4*KSZ)         // Kh, Kl, Vh, Vl = 18432
#define FNSTG 3
#define FSMEM (2*FQBUF + FNSTG*FSTG2)  // 73728

__global__ __launch_bounds__(128, 3) void flashattn(
    const __half* __restrict__ qh, const __half* __restrict__ ql,
    const __half* __restrict__ kh, const __half* __restrict__ kl,
    const __half* __restrict__ vh, const __half* __restrict__ vl,
    const __nv_bfloat16* __restrict__ madd,
    __half* __restrict__ cth, __half* __restrict__ ctl)
{
    extern __shared__ char smem[];
    const uint32_t su = smem_u32(smem);
    const int tid = threadIdx.x, lane = tid & 31, warp = tid >> 5;
    const int q0 = blockIdx.x * 64, bh = blockIdx.y;
    const int b = bh / NH, h = bh % NH;
    const int wr = warp * 16;

    const char* Qh = (const char*)(qh + ((size_t)b*SS + q0)*HH + h*DH);
    const char* Ql = (const char*)(ql + ((size_t)b*SS + q0)*HH + h*DH);
    const char* Kh = (const char*)(kh + ((size_t)b*SS)*HH + h*DH);
    const char* Kl = (const char*)(kl + ((size_t)b*SS)*HH + h*DH);
    const char* Vh = (const char*)(vh + ((size_t)b*SS)*HH + h*DH);
    const char* Vl = (const char*)(vl + ((size_t)b*SS)*HH + h*DH);

    #pragma unroll
    for (int c = 0; c < 4; c++) {
        int idx = tid + c*128;
        int row = idx >> 3, chn = idx & 7;
        uint32_t dst = su + row*QROW + chn*16;
        size_t so = (size_t)row*1536 + chn*16;
        cpa16(dst,         Qh + so);
        cpa16(dst + FQBUF, Ql + so);
    }
    CP_COMMIT();

    auto load_kv = [&](int j, int s) {
        uint32_t sb = su + 2*FQBUF + s*FSTG2;
        int k0 = j * 32;
        #pragma unroll
        for (int c = 0; c < 2; c++) {
            int idx = tid + c*128;
            int row = idx >> 3, chn = idx & 7;
            uint32_t dst = sb + row*KROW + chn*16;
            size_t ko = (size_t)(k0 + row)*1536 + chn*16;
            cpa16(dst,         Kh + ko);
            cpa16(dst +   KSZ, Kl + ko);
            cpa16(dst + 2*KSZ, Vh + ko);
            cpa16(dst + 3*KSZ, Vl + ko);
        }
    };
    load_kv(0, 0); CP_COMMIT();
    load_kv(1, 1); CP_COMMIT();

    asm volatile("cp.async.wait_group 2;" ::: "memory");
    __syncthreads();

    uint32_t qhf[4][4], qlf[4][4];
    {
        uint32_t abase = su + (uint32_t)(wr + (lane & 15))*QROW + (lane >> 4)*16;
        #pragma unroll
        for (int kc = 0; kc < 4; kc++) {
            ldsm4(qhf[kc], abase + kc*32);
            ldsm4(qlf[kc], abase + FQBUF + kc*32);
        }
    }

    float o[8][4];
    #pragma unroll
    for (int j = 0; j < 8; j++)
        #pragma unroll
        for (int r = 0; r < 4; r++) o[j][r] = 0.f;
    float m0 = -1e30f, m1 = -1e30f, l0 = 0.f, l1 = 0.f;

    const int r = lane >> 2;
    const int colb = (lane & 3) * 2;
    const __nv_bfloat16* mrow0 = madd + ((size_t)b*SS + (q0 + wr + r))*SS;
    const __nv_bfloat16* mrow8 = mrow0 + 8*SS;
    const uint32_t rowsel = (uint32_t)((((lane >> 4) & 1) << 3) + (lane & 7));
    const uint32_t bKoff = rowsel*KROW + ((lane >> 3) & 1)*16;
    const uint32_t bVoff = (uint32_t)(lane & 15)*KROW + ((lane >> 4) & 1)*16;

    for (int i = 0; i < 32; i++) {
        asm volatile("cp.async.wait_group 1;" ::: "memory");
        __syncthreads();
        if (i + 2 < 32) load_kv(i + 2, (i + 2) % 3);
        CP_COMMIT();

        const uint32_t sb = su + 2*FQBUF + (i % 3)*FSTG2;
        const int k0 = i * 32;

        float sc_[4][4];
        #pragma unroll
        for (int j = 0; j < 4; j++)
            #pragma unroll
            for (int t = 0; t < 4; t++) sc_[j][t] = 0.f;
        #pragma unroll
        for (int kc = 0; kc < 4; kc++) {
            uint32_t fh0[4], fl0[4], fh1[4], fl1[4];
            ldsm4(fh0, sb + bKoff + kc*32);
            ldsm4(fl0, sb + KSZ + bKoff + kc*32);
            ldsm4(fh1, sb + 16*KROW + bKoff + kc*32);
            ldsm4(fl1, sb + KSZ + 16*KROW + bKoff + kc*32);
            mma16816(sc_[0], qhf[kc], fh0);
            mma16816(sc_[1], qhf[kc], fh0+2);
            mma16816(sc_[2], qhf[kc], fh1);
            mma16816(sc_[3], qhf[kc], fh1+2);
            mma16816(sc_[0], qhf[kc], fl0);
            mma16816(sc_[1], qhf[kc], fl0+2);
            mma16816(sc_[2], qhf[kc], fl1);
            mma16816(sc_[3], qhf[kc], fl1+2);
            mma16816(sc_[0], qlf[kc], fh0);
            mma16816(sc_[1], qlf[kc], fh0+2);
            mma16816(sc_[2], qlf[kc], fh1);
            mma16816(sc_[3], qlf[kc], fh1+2);
        }
        #pragma unroll
        for (int j = 0; j < 4; j++) {
            int kc2 = k0 + j*8 + colb;
            __nv_bfloat162 ma = *(const __nv_bfloat162*)(mrow0 + kc2);
            __nv_bfloat162 mb = *(const __nv_bfloat162*)(mrow8 + kc2);
            float2 fa = __bfloat1622float2(ma);
            float2 fb = __bfloat1622float2(mb);
            sc_[j][0] = sc_[j][0]*0.125f + fa.x;
            sc_[j][1] = sc_[j][1]*0.125f + fa.y;
            sc_[j][2] = sc_[j][2]*0.125f + fb.x;
            sc_[j][3] = sc_[j][3]*0.125f + fb.y;
        }
        float mx0 = -1e30f, mx1 = -1e30f;
        #pragma unroll
        for (int j = 0; j < 4; j++) {
            mx0 = fmaxf(mx0, fmaxf(sc_[j][0], sc_[j][1]));
            mx1 = fmaxf(mx1, fmaxf(sc_[j][2], sc_[j][3]));
        }
        mx0 = fmaxf(mx0, __shfl_xor_sync(0xffffffffu, mx0, 1));
        mx0 = fmaxf(mx0, __shfl_xor_sync(0xffffffffu, mx0, 2));
        mx1 = fmaxf(mx1, __shfl_xor_sync(0xffffffffu, mx1, 1));
        mx1 = fmaxf(mx1, __shfl_xor_sync(0xffffffffu, mx1, 2));
        float mn0 = fmaxf(m0, mx0), mn1 = fmaxf(m1, mx1);
        float sf0 = __expf(m0 - mn0), sf1 = __expf(m1 - mn1);
        m0 = mn0; m1 = mn1;
        float rs0 = 0.f, rs1 = 0.f;
        #pragma unroll
        for (int j = 0; j < 4; j++) {
            sc_[j][0] = __expf(sc_[j][0] - mn0);
            sc_[j][1] = __expf(sc_[j][1] - mn0);
            sc_[j][2] = __expf(sc_[j][2] - mn1);
            sc_[j][3] = __expf(sc_[j][3] - mn1);
            rs0 += sc_[j][0] + sc_[j][1];
            rs1 += sc_[j][2] + sc_[j][3];
        }
        rs0 += __shfl_xor_sync(0xffffffffu, rs0, 1);
        rs0 += __shfl_xor_sync(0xffffffffu, rs0, 2);
        rs1 += __shfl_xor_sync(0xffffffffu, rs1, 1);
        rs1 += __shfl_xor_sync(0xffffffffu, rs1, 2);
        l0 = l0*sf0 + rs0;
        l1 = l1*sf1 + rs1;
        #pragma unroll
        for (int j = 0; j < 8; j++) {
            o[j][0] *= sf0; o[j][1] *= sf0; o[j][2] *= sf1; o[j][3] *= sf1;
        }
        uint32_t phf[2][4], plf[2][4];
        #pragma unroll
        for (int kc = 0; kc < 2; kc++) {
            #pragma unroll
            for (int half = 0; half < 2; half++) {
                int j = 2*kc + half;
                __half h0 = __float2half_rn(sc_[j][0]);
                __half h1 = __float2half_rn(sc_[j][1]);
                __half h2 = __float2half_rn(sc_[j][2]);
                __half h3 = __float2half_rn(sc_[j][3]);
                phf[kc][half*2+0] = pack_h2(h0, h1);
                phf[kc][half*2+1] = pack_h2(h2, h3);
                plf[kc][half*2+0] = pack_h2(
                    __float2half_rn(sc_[j][0] - __half2float(h0)),
                    __float2half_rn(sc_[j][1] - __half2float(h1)));
                plf[kc][half*2+1] = pack_h2(
                    __float2half_rn(sc_[j][2] - __half2float(h2)),
                    __float2half_rn(sc_[j][3] - __half2float(h3)));
            }
        }
        #pragma unroll
        for (int kc = 0; kc < 2; kc++) {
            #pragma unroll
            for (int ntp = 0; ntp < 4; ntp += 2) {
                uint32_t fha[4], fla[4], fhb[4], flb[4];
                ldsm4t(fha, sb + 2*KSZ + kc*16*KROW + bVoff + ntp*32);
                ldsm4t(fla, sb + 3*KSZ + kc*16*KROW + bVoff + ntp*32);
                ldsm4t(fhb, sb + 2*KSZ + kc*16*KROW + bVoff + (ntp+1)*32);
                ldsm4t(flb, sb + 3*KSZ + kc*16*KROW + bVoff + (ntp+1)*32);
                mma16816(o[2*ntp],   phf[kc], fha);
                mma16816(o[2*ntp+1], phf[kc], fha+2);
                mma16816(o[2*ntp+2], phf[kc], fhb);
                mma16816(o[2*ntp+3], phf[kc], fhb+2);
                mma16816(o[2*ntp],   phf[kc], fla);
                mma16816(o[2*ntp+1], phf[kc], fla+2);
                mma16816(o[2*ntp+2], phf[kc], flb);
                mma16816(o[2*ntp+3], phf[kc], flb+2);
                mma16816(o[2*ntp],   plf[kc], fha);
                mma16816(o[2*ntp+1], plf[kc], fha+2);
                mma16816(o[2*ntp+2], plf[kc], fhb);
                mma16816(o[2*ntp+3], plf[kc], fhb+2);
            }
        }
    }

    float inv0 = 1.f / l0, inv1 = 1.f / l1;
    size_t base0 = ((size_t)b*SS + (q0 + wr + r))*HH + h*DH;
    size_t base8 = base0 + (size_t)8*HH;
    #pragma unroll
    for (int j = 0; j < 8; j++) {
        int col = j*8 + colb;
        float a0 = o[j][0]*inv0, a1 = o[j][1]*inv0;
        float a2 = o[j][2]*inv1, a3 = o[j][3]*inv1;
        __half h0 = __float2half_rn(a0), h1 = __float2half_rn(a1);
        __half h2 = __float2half_rn(a2), h3 = __float2half_rn(a3);
        *(uint32_t*)(cth + base0 + col) = pack_h2(h0, h1);
        *(uint32_t*)(ctl + base0 + col) = pack_h2(
            __float2half_rn(a0 - __half2float(h0)),
            __float2half_rn(a1 - __half2float(h1)));
        *(uint32_t*)(cth + base8 + col) = pack_h2(h2, h3);
        *(uint32_t*)(ctl + base8 + col) = pack_h2(
            __float2half_rn(a2 - __half2float(h2)),
            __float2half_rn(a3 - __half2float(h3)));
    }
}

// ---------------- mask -> bf16 additive prebake ----------------
__global__ __launch_bounds__(256) void maskprep(const int* __restrict__ mask,
                                                __nv_bfloat16* __restrict__ madd, int n4)
{
    int i = blockIdx.x * 256 + threadIdx.x;
    if (i >= n4) return;
    int4 m = ((const int4*)mask)[i];
    __nv_bfloat16 z = __float2bfloat16(0.f), neg = __float2bfloat16(-10000.f);
    __nv_bfloat162 a = __halves2bfloat162(m.x ? z : neg, m.y ? z : neg);
    __nv_bfloat162 b = __halves2bfloat162(m.z ? z : neg, m.w ? z : neg);
    uint2 o;
    o.x = *(uint32_t*)&a; o.y = *(uint32_t*)&b;
    *(uint2*)(madd + (size_t)i*4) = o;
}

// ---------------- split fp32 -> fp16 hi/lo (only for initial x) ----------------
__global__ __launch_bounds__(256) void split_kernel(const float* __restrict__ x,
    __half* __restrict__ hi, __half* __restrict__ lo, int n4)
{
    int i = blockIdx.x * 256 + threadIdx.x;
    if (i >= n4) return;
    float4 v = ((const float4*)x)[i];
    __half h0 = __float2half_rn(v.x), h1 = __float2half_rn(v.y);
    __half h2 = __float2half_rn(v.z), h3 = __float2half_rn(v.w);
    uint2 H, L;
    H.x = pack_h2(h0, h1); H.y = pack_h2(h2, h3);
    L.x = pack_h2(__float2half_rn(v.x - __half2float(h0)),
                  __float2half_rn(v.y - __half2float(h1)));
    L.y = pack_h2(__float2half_rn(v.z - __half2float(h2)),
                  __float2half_rn(v.w - __half2float(h3)));
    *(uint2*)(hi + (size_t)i*4) = H;
    *(uint2*)(lo + (size_t)i*4) = L;
}

// ---------------- batched weight transpose (single fp16) ----------------
__global__ __launch_bounds__(256) void wtrans_all(
    const float* __restrict__ Wq, const float* __restrict__ Wk,
    const float* __restrict__ Wv, const float* __restrict__ Wao,
    const float* __restrict__ Wi, const float* __restrict__ Wfo,
    __half* __restrict__ wh)
{
    __shared__ float t[64][33];
    const int tid = threadIdx.x;
    const int l = blockIdx.z;
    int x = blockIdx.x;

    const float* W; int K_, N_; size_t off;
    if (x < 1152) {
        int m = x / 288; x -= m * 288;
        K_ = HH; N_ = HH;
        W = (m == 0 ? Wq : m == 1 ? Wk : m == 2 ? Wv : Wao) + (size_t)l * HH * HH;
        off = (m == 0 ? WQOFF : m == 1 ? WKOFF : m == 2 ? WVOFF : WAOOFF);
    } else if (x < 2304) {
        x -= 1152; K_ = HH; N_ = FF;
        W = Wi + (size_t)l * HH * FF; off = WIOFF;
    } else {
        x -= 2304; K_ = FF; N_ = HH;
        W = Wfo + (size_t)l * FF * HH; off = WFOOFF;
    }
    const int ntn = N_ >> 5;
    const int k0 = (x / ntn) << 6, n0 = (x % ntn) << 5;

    {
        int r = tid >> 5, c = tid & 31;
        #pragma unroll
        for (int i = 0; i < 8; i++)
            t[r + i*8][c] = W[(size_t)(k0 + r + i*8) * N_ + n0 + c];
    }
    __syncthreads();

    __half* hi = wh + (size_t)l * LSTRIDE + off;
    #pragma unroll
    for (int it = 0; it < 2; it++) {
        int idx = tid + it * 256;
        int nl = idx >> 4, kq = idx & 15;
        float v0 = t[kq*4+0][nl], v1 = t[kq*4+1][nl];
        float v2 = t[kq*4+2][nl], v3 = t[kq*4+3][nl];
        uint2 hv;
        hv.x = pack_h2(__float2half_rn(v0), __float2half_rn(v1));
        hv.y = pack_h2(__float2half_rn(v2), __float2half_rn(v3));
        size_t base = (size_t)(n0 + nl) * K_ + k0 + kq*4;
        *(uint2*)(hi + base) = hv;
    }
}

// ---------------- launch ----------------
extern "C" void kernel_launch(void* const* d_in, const int* in_sizes, int n_in,
                              void* d_out, int out_size)
{
    const float* x    = (const float*)d_in[0];
    const int*   mask = (const int*)  d_in[1];
    const float* Wq   = (const float*)d_in[2];
    const float* bq   = (const float*)d_in[3];
    const float* Wk   = (const float*)d_in[4];
    const float* bk   = (const float*)d_in[5];
    const float* Wv   = (const float*)d_in[6];
    const float* bv   = (const float*)d_in[7];
    const float* Wao  = (const float*)d_in[8];
    const float* bao  = (const float*)d_in[9];
    const float* g1   = (const float*)d_in[10];
    const float* b1   = (const float*)d_in[11];
    const float* Wi   = (const float*)d_in[12];
    const float* bi   = (const float*)d_in[13];
    const float* Wfo  = (const float*)d_in[14];
    const float* bfo  = (const float*)d_in[15];
    const float* g2   = (const float*)d_in[16];
    const float* b2   = (const float*)d_in[17];

    float *h_, *attn_, *p0_, *p1_, *p2_;
    __half *hh_, *hl_, *qh_, *ql_, *kh_, *kl_, *vh_, *vl_;
    __half *cth_, *ctl_, *aah_, *aal_, *ih_, *il_, *wh_;
    __nv_bfloat16 *madd_;
    cudaGetSymbolAddress((void**)&h_,    g_h);
    cudaGetSymbolAddress((void**)&attn_, g_attn);
    cudaGetSymbolAddress((void**)&p0_,   g_p0);
    cudaGetSymbolAddress((void**)&p1_,   g_p1);
    cudaGetSymbolAddress((void**)&p2_,   g_p2);
    cudaGetSymbolAddress((void**)&hh_,   g_hh);
    cudaGetSymbolAddress((void**)&hl_,   g_hl);
    cudaGetSymbolAddress((void**)&qh_,   g_qh);
    cudaGetSymbolAddress((void**)&ql_,   g_ql);
    cudaGetSymbolAddress((void**)&kh_,   g_kh);
    cudaGetSymbolAddress((void**)&kl_,   g_kl);
    cudaGetSymbolAddress((void**)&vh_,   g_vh);
    cudaGetSymbolAddress((void**)&vl_,   g_vl);
    cudaGetSymbolAddress((void**)&cth_,  g_cth);
    cudaGetSymbolAddress((void**)&ctl_,  g_ctl);
    cudaGetSymbolAddress((void**)&aah_,  g_aah);
    cudaGetSymbolAddress((void**)&aal_,  g_aal);
    cudaGetSymbolAddress((void**)&ih_,   g_ih);
    cudaGetSymbolAddress((void**)&il_,   g_il);
    cudaGetSymbolAddress((void**)&wh_,   g_wh);
    cudaGetSymbolAddress((void**)&madd_, g_madd);

    cudaFuncSetAttribute(gemm_tc,
                         cudaFuncAttributeMaxDynamicSharedMemorySize, GEMM_SMEM);
    cudaFuncSetAttribute(flashattn,
                         cudaFuncAttributeMaxDynamicSharedMemorySize, FSMEM);

    const int M = BB * SS;  // 2048
    const int n4 = M * HH / 4;
    const int mn4 = BB * SS * SS / 4;

    wtrans_all<<<dim3(3456, 1, NL), 256>>>(Wq, Wk, Wv, Wao, Wi, Wfo, wh_);
    maskprep<<<(mn4 + 255)/256, 256>>>(mask, madd_, mn4);
    split_kernel<<<(n4 + 255)/256, 256>>>(x, hh_, hl_, n4);

    for (int l = 0; l < NL; l++) {
        const float* hin = (l == 0) ? x : h_;
        size_t lo = (size_t)l * LSTRIDE;

        // QKV -> fp16 hi/lo outputs
        {
            GemmArgs a = {};
            a.ah = hh_; a.al = hl_;
            a.bh0 = wh_+lo+WQOFF; a.bh1 = wh_+lo+WKOFF; a.bh2 = wh_+lo+WVOFF;
            a.bias0 = bq + l*HH; a.bias1 = bk + l*HH; a.bias2 = bv + l*HH;
            a.ch0 = qh_; a.cl0 = ql_; a.ch1 = kh_; a.cl1 = kl_; a.ch2 = vh_; a.cl2 = vl_;
            a.K = HH; a.N = HH; a.gelu = 0; a.outbf = 1; a.Kld = HH; a.ksplit = 0;
            gemm_tc<<<dim3(HH/128, M/128, 3), 512, GEMM_SMEM>>>(a);
        }

        flashattn<<<dim3(SS/64, BB*NH), 128, FSMEM>>>(qh_, ql_, kh_, kl_, vh_, vl_,
                                                      madd_, cth_, ctl_);

        // AO proj: split-K=3 -> partials -> fused reduce+LN
        {
            GemmArgs a = {};
            a.ah = cth_; a.al = ctl_;
            a.bh0 = wh_+lo+WAOOFF; a.bh1 = a.bh0; a.bh2 = a.bh0;
            a.c0 = p0_; a.c1 = p1_; a.c2 = p2_;
            a.K = 256; a.N = HH; a.gelu = 0; a.outbf = 0; a.Kld = HH; a.ksplit = 1;
            gemm_tc<<<dim3(HH/128, M/128, 3), 512, GEMM_SMEM>>>(a);
        }
        reduce_ln<<<M, 256>>>(p0_, p1_, p2_, bao + l*HH, hin,
                              g1 + l*HH, b1 + l*HH, attn_, aah_, aal_);

        // FFN1 (gelu) -> fp16 hi/lo
        {
            GemmArgs a = {};
            a.ah = aah_; a.al = aal_;
            a.bh0 = wh_+lo+WIOFF; a.bh1 = a.bh0; a.bh2 = a.bh0;
            a.bias0 = bi + l*FF; a.bias1 = a.bias0; a.bias2 = a.bias0;
            a.ch0 = ih_; a.cl0 = il_; a.ch1 = ih_; a.cl1 = il_; a.ch2 = ih_; a.cl2 = il_;
            a.K = HH; a.N = FF; a.gelu = 1; a.outbf = 1; a.Kld = HH; a.ksplit = 0;
            gemm_tc<<<dim3(FF/128, M/128, 1), 512, GEMM_SMEM>>>(a);
        }

        // FFN2: split-K=3 -> partials -> fused reduce+LN
        {
            GemmArgs a = {};
            a.ah = ih_; a.al = il_;
            a.bh0 = wh_+lo+WFOOFF; a.bh1 = a.bh0; a.bh2 = a.bh0;
            a.c0 = p0_; a.c1 = p1_; a.c2 = p2_;
            a.K = 1024; a.N = HH; a.gelu = 0; a.outbf = 0; a.Kld = FF; a.ksplit = 1;
            gemm_tc<<<dim3(HH/128, M/128, 3), 512, GEMM_SMEM>>>(a);
        }
        if (l == NL - 1) {
            reduce_ln<<<M, 256>>>(p0_, p1_, p2_, bfo + l*HH, attn_,
                                  g2 + l*HH, b2 + l*HH, (float*)d_out,
                                  (__half*)nullptr, (__half*)nullptr);
        } else {
            reduce_ln<<<M, 256>>>(p0_, p1_, p2_, bfo + l*HH, attn_,
                                  g2 + l*HH, b2 + l*HH, h_, hh_, hl_);
        }
    }
}

// round 15
// speedup vs baseline: 1.4170x; 1.1457x over previous
#include <cuda_runtime.h>
#include <cuda_bf16.h>
#include <cuda_fp16.h>
#include <math.h>
#include <stdint.h>

#define BB 2
#define SS 1024
#define HH 768
#define NH 12
#define DH 64
#define FF 3072
#define NL 4

// ---------------- scratch (device globals; no allocation allowed) ----------------
__device__ float g_h[BB*SS*HH];
__device__ float g_attn[BB*SS*HH];
__device__ float g_p0[BB*SS*HH];
__device__ float g_p1[BB*SS*HH];
__device__ float g_p2[BB*SS*HH];

__device__ __half g_hh[BB*SS*HH], g_hl[BB*SS*HH];
__device__ __half g_qh[BB*SS*HH], g_ql[BB*SS*HH];
__device__ __half g_kh[BB*SS*HH], g_kl[BB*SS*HH];
__device__ __half g_vh[BB*SS*HH], g_vl[BB*SS*HH];
__device__ __half g_cth[BB*SS*HH], g_ctl[BB*SS*HH];
__device__ __half g_aah[BB*SS*HH], g_aal[BB*SS*HH];
__device__ __half g_ih[BB*SS*FF], g_il[BB*SS*FF];
__device__ __nv_bfloat16 g_madd[(size_t)BB*SS*SS];   // (1-mask)*-10000 as bf16

// transposed weights per layer (single fp16): [wq wk wv wao wi wfo], each [N][K] row-major
#define WQOFF  0
#define WKOFF  589824
#define WVOFF  1179648
#define WAOOFF 1769472
#define WIOFF  2359296
#define WFOOFF 4718592
#define LSTRIDE 7077888
__device__ __half g_wh[(size_t)NL*LSTRIDE];

// ---------------- PTX helpers ----------------
__device__ __forceinline__ uint32_t smem_u32(const void* p) {
    uint32_t a;
    asm("{ .reg .u64 t; cvta.to.shared.u64 t, %1; cvt.u32.u64 %0, t; }" : "=r"(a) : "l"(p));
    return a;
}
__device__ __forceinline__ void cpa16(uint32_t dst, const void* src) {
    asm volatile("cp.async.cg.shared.global [%0], [%1], 16;" :: "r"(dst), "l"(src));
}
#define CP_COMMIT() asm volatile("cp.async.commit_group;" ::: "memory")

__device__ __forceinline__ void ldsm4(uint32_t* r, uint32_t a) {
    asm volatile("ldmatrix.sync.aligned.m8n8.x4.shared.b16 {%0,%1,%2,%3}, [%4];"
        : "=r"(r[0]), "=r"(r[1]), "=r"(r[2]), "=r"(r[3]) : "r"(a));
}
__device__ __forceinline__ void ldsm4t(uint32_t* r, uint32_t a) {
    asm volatile("ldmatrix.sync.aligned.m8n8.x4.trans.shared.b16 {%0,%1,%2,%3}, [%4];"
        : "=r"(r[0]), "=r"(r[1]), "=r"(r[2]), "=r"(r[3]) : "r"(a));
}
__device__ __forceinline__ void mma16816(float* c, const uint32_t* a, const uint32_t* b) {
    asm("mma.sync.aligned.m16n8k16.row.col.f32.f16.f16.f32 "
        "{%0,%1,%2,%3}, {%4,%5,%6,%7}, {%8,%9}, {%0,%1,%2,%3};"
        : "+f"(c[0]), "+f"(c[1]), "+f"(c[2]), "+f"(c[3])
        : "r"(a[0]), "r"(a[1]), "r"(a[2]), "r"(a[3]), "r"(b[0]), "r"(b[1]));
}
__device__ __forceinline__ uint32_t pack_h2(__half a, __half b) {
    __half2 t = __halves2half2(a, b);
    return *(uint32_t*)&t;
}

// ---------------- fp16 GEMM: C = (Ah[+Al]) @ W16^T; 128x128 tile, 512 thr, K-chunk 64 ----
struct GemmArgs {
    const __half *ah, *al;
    const __half *bh0, *bh1, *bh2;
    const float *bias0, *bias1, *bias2;
    const float *resid;
    float *c0, *c1, *c2;
    __half *ch0, *cl0, *ch1, *cl1, *ch2, *cl2;
    int K, N, gelu, outbf, Kld, ksplit, x1;
};

#define ROWB 144               // 128B data + 16B pad
#define ABUF 18432             // 128 rows * 144B
#define STGB (3*ABUF)          // Ah, Al, Bh = 55296
#define NSTG 3
#define GEMM_SMEM (NSTG*STGB)  // 165888

__global__ __launch_bounds__(512) void gemm_tc(GemmArgs g) {
    extern __shared__ char smem[];
    const uint32_t su = smem_u32(smem);
    const int tid = threadIdx.x;
    const int lane = tid & 31, warp = tid >> 5;
    const int warpM = warp & 3, warpN = warp >> 2;
    const int m0 = blockIdx.y << 7, n0 = blockIdx.x << 7;

    const __half *bh; const float* bias; float* C;
    __half *CH, *CL;
    if (blockIdx.z == 0)      { bh=g.bh0; bias=g.bias0; C=g.c0; CH=g.ch0; CL=g.cl0; }
    else if (blockIdx.z == 1) { bh=g.bh1; bias=g.bias1; C=g.c1; CH=g.ch1; CL=g.cl1; }
    else                      { bh=g.bh2; bias=g.bias2; C=g.c2; CH=g.ch2; CL=g.cl2; }
    const int K = g.K, N = g.N, nk = K >> 6;
    const int kbase = g.ksplit ? (int)blockIdx.z * K : 0;
    const int x1 = g.x1;

    const int ldg_row = tid >> 3, ldg_c = tid & 7;
    const size_t ldab = (size_t)g.Kld * 2;
    const char* pAh = (const char*)g.ah + ((size_t)(m0 + ldg_row)) * ldab + (size_t)kbase*2 + ldg_c * 16;
    const char* pAl = (const char*)g.al + ((size_t)(m0 + ldg_row)) * ldab + (size_t)kbase*2 + ldg_c * 16;
    const char* pBh = (const char*)bh   + ((size_t)(n0 + ldg_row)) * ldab + (size_t)kbase*2 + ldg_c * 16;
    const size_t rowskip = 64 * ldab;
    const uint32_t sdst = ldg_row * ROWB + ldg_c * 16;

    auto load_chunk = [&](int j, int s) {
        uint32_t sb = su + s * STGB + sdst;
        size_t go = (size_t)j * 128;
        cpa16(sb,                        pAh + go);
        cpa16(sb + 64*ROWB,              pAh + rowskip + go);
        if (!x1) {
            cpa16(sb +   ABUF,           pAl + go);
            cpa16(sb +   ABUF + 64*ROWB, pAl + rowskip + go);
        }
        cpa16(sb + 2*ABUF,               pBh + go);
        cpa16(sb + 2*ABUF + 64*ROWB,     pBh + rowskip + go);
    };

    load_chunk(0, 0); CP_COMMIT();
    load_chunk(1, 1); CP_COMMIT();

    float acc[2][4][4];
    #pragma unroll
    for (int i = 0; i < 2; i++)
        #pragma unroll
        for (int j = 0; j < 4; j++)
            #pragma unroll
            for (int r = 0; r < 4; r++) acc[i][j][r] = 0.f;

    const uint32_t a_off = (uint32_t)(warpM*32 + (lane & 15)) * ROWB + (lane >> 4) * 16;
    const uint32_t b_off = (uint32_t)(warpN*32 + (((lane >> 4) & 1) << 3) + (lane & 7)) * ROWB
                         + ((lane >> 3) & 1) * 16;

    for (int i = 0; i < nk; i++) {
        asm volatile("cp.async.wait_group 1;" ::: "memory");
        __syncthreads();
        int j = i + 2;
        if (j < nk) load_chunk(j, j % NSTG);
        CP_COMMIT();

        uint32_t base = su + (i % NSTG) * STGB;
        #pragma unroll
        for (int ks = 0; ks < 4; ks++) {
            uint32_t ko = ks * 32;
            uint32_t ah0[4], ah1[4], al0[4], al1[4];
            uint32_t bhf0[4], bhf1[4];
            ldsm4(ah0, base + a_off + ko);
            ldsm4(ah1, base + a_off + 16*ROWB + ko);
            if (!x1) {
                ldsm4(al0, base + ABUF + a_off + ko);
                ldsm4(al1, base + ABUF + a_off + 16*ROWB + ko);
            }
            ldsm4(bhf0, base + 2*ABUF + b_off + ko);
            ldsm4(bhf1, base + 2*ABUF + b_off + 16*ROWB + ko);
            uint32_t* AH[2] = {ah0, ah1};
            uint32_t* AL[2] = {al0, al1};
            #pragma unroll
            for (int mt = 0; mt < 2; mt++) {
                mma16816(acc[mt][0], AH[mt], bhf0);
                mma16816(acc[mt][1], AH[mt], bhf0+2);
                mma16816(acc[mt][2], AH[mt], bhf1);
                mma16816(acc[mt][3], AH[mt], bhf1+2);
                if (!x1) {
                    mma16816(acc[mt][0], AL[mt], bhf0);
                    mma16816(acc[mt][1], AL[mt], bhf0+2);
                    mma16816(acc[mt][2], AL[mt], bhf1);
                    mma16816(acc[mt][3], AL[mt], bhf1+2);
                }
            }
        }
    }

    const int erow = m0 + warpM*32 + (lane >> 2);
    const int ecol = n0 + warpN*32 + (lane & 3)*2;
    #pragma unroll
    for (int mt = 0; mt < 2; mt++) {
        #pragma unroll
        for (int nt = 0; nt < 4; nt++) {
            int c = ecol + nt*8;
            float b0 = bias ? bias[c] : 0.f, b1 = bias ? bias[c+1] : 0.f;
            #pragma unroll
            for (int half = 0; half < 2; half++) {
                int r = erow + mt*16 + half*8;
                float o0 = acc[mt][nt][half*2+0] + b0;
                float o1 = acc[mt][nt][half*2+1] + b1;
                if (g.resid) {
                    float2 rv = *(const float2*)(g.resid + (size_t)r * N + c);
                    o0 += rv.x; o1 += rv.y;
                }
                if (g.gelu) {
                    o0 = 0.5f * o0 * (1.0f + erff(o0 * 0.70710678118654752f));
                    o1 = 0.5f * o1 * (1.0f + erff(o1 * 0.70710678118654752f));
                }
                if (g.outbf) {
                    __half h0 = __float2half_rn(o0), h1 = __float2half_rn(o1);
                    __half l0 = __float2half_rn(o0 - __half2float(h0));
                    __half l1 = __float2half_rn(o1 - __half2float(h1));
                    *(uint32_t*)(CH + (size_t)r * N + c) = pack_h2(h0, h1);
                    *(uint32_t*)(CL + (size_t)r * N + c) = pack_h2(l0, l1);
                } else {
                    float2 ov; ov.x = o0; ov.y = o1;
                    *(float2*)(C + (size_t)r * N + c) = ov;
                }
            }
        }
    }
}

// ---------------- fused split-K reduce + LayerNorm (+ optional fp16 hi/lo out) ----------------
__global__ __launch_bounds__(256) void reduce_ln(
    const float* __restrict__ p0, const float* __restrict__ p1,
    const float* __restrict__ p2, const float* __restrict__ bias,
    const float* __restrict__ resid,
    const float* __restrict__ g, const float* __restrict__ b,
    float* __restrict__ out,
    __half* __restrict__ oh, __half* __restrict__ ol)
{
    const int row = blockIdx.x;
    const int tid = threadIdx.x;
    const size_t base = (size_t)row * HH;

    float v0, v1, v2;
    {
        int i0 = tid, i1 = tid + 256, i2 = tid + 512;
        v0 = p0[base+i0] + p1[base+i0] + p2[base+i0] + bias[i0] + resid[base+i0];
        v1 = p0[base+i1] + p1[base+i1] + p2[base+i1] + bias[i1] + resid[base+i1];
        v2 = p0[base+i2] + p1[base+i2] + p2[base+i2] + bias[i2] + resid[base+i2];
    }

    __shared__ float red[8];
    float s = v0 + v1 + v2;
    #pragma unroll
    for (int o2 = 16; o2; o2 >>= 1) s += __shfl_xor_sync(0xffffffffu, s, o2);
    if ((tid & 31) == 0) red[tid >> 5] = s;
    __syncthreads();
    float tot = 0.f;
    #pragma unroll
    for (int i = 0; i < 8; i++) tot += red[i];
    float mean = tot * (1.0f / 768.0f);

    float d0 = v0 - mean, d1 = v1 - mean, d2 = v2 - mean;
    float sq = d0*d0 + d1*d1 + d2*d2;
    __syncthreads();
    #pragma unroll
    for (int o2 = 16; o2; o2 >>= 1) sq += __shfl_xor_sync(0xffffffffu, sq, o2);
    if ((tid & 31) == 0) red[tid >> 5] = sq;
    __syncthreads();
    float tot2 = 0.f;
    #pragma unroll
    for (int i = 0; i < 8; i++) tot2 += red[i];
    float rstd = rsqrtf(tot2 * (1.0f / 768.0f) + 1e-12f);

    float r0 = d0 * rstd * g[tid]       + b[tid];
    float r1 = d1 * rstd * g[tid + 256] + b[tid + 256];
    float r2 = d2 * rstd * g[tid + 512] + b[tid + 512];
    out[base + tid] = r0; out[base + tid + 256] = r1; out[base + tid + 512] = r2;
    if (oh) {
        __half h0 = __float2half_rn(r0);
        __half h1 = __float2half_rn(r1);
        __half h2 = __float2half_rn(r2);
        oh[base + tid] = h0;       ol[base + tid]       = __float2half_rn(r0 - __half2float(h0));
        oh[base + tid + 256] = h1; ol[base + tid + 256] = __float2half_rn(r1 - __half2float(h1));
        oh[base + tid + 512] = h2; ol[base + tid + 512] = __float2half_rn(r2 - __half2float(h2));
    }
}

// ---------------- flash attention x2: Q,P exact (hi+lo), K,V single fp16 ----
// K-tile 32, 3-stage pipeline, 4 CTAs/SM.
#define QROW 144
#define FQBUF 9216            // 64*144
#define KROW 144
#define KSZ  4608             // 32*144
#define FSTG2 (2*KSZ)         // Kh, Vh = 9216
#define FNSTG 3
#define FSMEM (2*FQBUF + FNSTG*FSTG2)  // 46080

__global__ __launch_bounds__(128, 4) void flashattn(
    const __half* __restrict__ qh, const __half* __restrict__ ql,
    const __half* __restrict__ kh, const __half* __restrict__ vh,
    const __nv_bfloat16* __restrict__ madd,
    __half* __restrict__ cth, __half* __restrict__ ctl)
{
    extern __shared__ char smem[];
    const uint32_t su = smem_u32(smem);
    const int tid = threadIdx.x, lane = tid & 31, warp = tid >> 5;
    const int q0 = blockIdx.x * 64, bh = blockIdx.y;
    const int b = bh / NH, h = bh % NH;
    const int wr = warp * 16;

    const char* Qh = (const char*)(qh + ((size_t)b*SS + q0)*HH + h*DH);
    const char* Ql = (const char*)(ql + ((size_t)b*SS + q0)*HH + h*DH);
    const char* Kh = (const char*)(kh + ((size_t)b*SS)*HH + h*DH);
    const char* Vh = (const char*)(vh + ((size_t)b*SS)*HH + h*DH);

    #pragma unroll
    for (int c = 0; c < 4; c++) {
        int idx = tid + c*128;
        int row = idx >> 3, chn = idx & 7;
        uint32_t dst = su + row*QROW + chn*16;
        size_t so = (size_t)row*1536 + chn*16;
        cpa16(dst,         Qh + so);
        cpa16(dst + FQBUF, Ql + so);
    }
    CP_COMMIT();

    auto load_kv = [&](int j, int s) {
        uint32_t sb = su + 2*FQBUF + s*FSTG2;
        int k0 = j * 32;
        #pragma unroll
        for (int c = 0; c < 2; c++) {
            int idx = tid + c*128;
            int row = idx >> 3, chn = idx & 7;
            uint32_t dst = sb + row*KROW + chn*16;
            size_t ko = (size_t)(k0 + row)*1536 + chn*16;
            cpa16(dst,       Kh + ko);
            cpa16(dst + KSZ, Vh + ko);
        }
    };
    load_kv(0, 0); CP_COMMIT();
    load_kv(1, 1); CP_COMMIT();

    asm volatile("cp.async.wait_group 2;" ::: "memory");
    __syncthreads();

    uint32_t qhf[4][4], qlf[4][4];
    {
        uint32_t abase = su + (uint32_t)(wr + (lane & 15))*QROW + (lane >> 4)*16;
        #pragma unroll
        for (int kc = 0; kc < 4; kc++) {
            ldsm4(qhf[kc], abase + kc*32);
            ldsm4(qlf[kc], abase + FQBUF + kc*32);
        }
    }

    float o[8][4];
    #pragma unroll
    for (int j = 0; j < 8; j++)
        #pragma unroll
        for (int r = 0; r < 4; r++) o[j][r] = 0.f;
    float m0 = -1e30f, m1 = -1e30f, l0 = 0.f, l1 = 0.f;

    const int r = lane >> 2;
    const int colb = (lane & 3) * 2;
    const __nv_bfloat16* mrow0 = madd + ((size_t)b*SS + (q0 + wr + r))*SS;
    const __nv_bfloat16* mrow8 = mrow0 + 8*SS;
    const uint32_t rowsel = (uint32_t)((((lane >> 4) & 1) << 3) + (lane & 7));
    const uint32_t bKoff = rowsel*KROW + ((lane >> 3) & 1)*16;
    const uint32_t bVoff = (uint32_t)(lane & 15)*KROW + ((lane >> 4) & 1)*16;

    for (int i = 0; i < 32; i++) {
        asm volatile("cp.async.wait_group 1;" ::: "memory");
        __syncthreads();
        if (i + 2 < 32) load_kv(i + 2, (i + 2) % 3);
        CP_COMMIT();

        const uint32_t sb = su + 2*FQBUF + (i % 3)*FSTG2;
        const int k0 = i * 32;

        // ---- S = (Qh+Ql) K16^T ----
        float sc_[4][4];
        #pragma unroll
        for (int j = 0; j < 4; j++)
            #pragma unroll
            for (int t = 0; t < 4; t++) sc_[j][t] = 0.f;
        #pragma unroll
        for (int kc = 0; kc < 4; kc++) {
            uint32_t fh0[4], fh1[4];
            ldsm4(fh0, sb + bKoff + kc*32);
            ldsm4(fh1, sb + 16*KROW + bKoff + kc*32);
            mma16816(sc_[0], qhf[kc], fh0);
            mma16816(sc_[1], qhf[kc], fh0+2);
            mma16816(sc_[2], qhf[kc], fh1);
            mma16816(sc_[3], qhf[kc], fh1+2);
            mma16816(sc_[0], qlf[kc], fh0);
            mma16816(sc_[1], qlf[kc], fh0+2);
            mma16816(sc_[2], qlf[kc], fh1);
            mma16816(sc_[3], qlf[kc], fh1+2);
        }
        #pragma unroll
        for (int j = 0; j < 4; j++) {
            int kc2 = k0 + j*8 + colb;
            __nv_bfloat162 ma = *(const __nv_bfloat162*)(mrow0 + kc2);
            __nv_bfloat162 mb = *(const __nv_bfloat162*)(mrow8 + kc2);
            float2 fa = __bfloat1622float2(ma);
            float2 fb = __bfloat1622float2(mb);
            sc_[j][0] = sc_[j][0]*0.125f + fa.x;
            sc_[j][1] = sc_[j][1]*0.125f + fa.y;
            sc_[j][2] = sc_[j][2]*0.125f + fb.x;
            sc_[j][3] = sc_[j][3]*0.125f + fb.y;
        }
        float mx0 = -1e30f, mx1 = -1e30f;
        #pragma unroll
        for (int j = 0; j < 4; j++) {
            mx0 = fmaxf(mx0, fmaxf(sc_[j][0], sc_[j][1]));
            mx1 = fmaxf(mx1, fmaxf(sc_[j][2], sc_[j][3]));
        }
        mx0 = fmaxf(mx0, __shfl_xor_sync(0xffffffffu, mx0, 1));
        mx0 = fmaxf(mx0, __shfl_xor_sync(0xffffffffu, mx0, 2));
        mx1 = fmaxf(mx1, __shfl_xor_sync(0xffffffffu, mx1, 1));
        mx1 = fmaxf(mx1, __shfl_xor_sync(0xffffffffu, mx1, 2));
        float mn0 = fmaxf(m0, mx0), mn1 = fmaxf(m1, mx1);
        float sf0 = __expf(m0 - mn0), sf1 = __expf(m1 - mn1);
        m0 = mn0; m1 = mn1;
        float rs0 = 0.f, rs1 = 0.f;
        #pragma unroll
        for (int j = 0; j < 4; j++) {
            sc_[j][0] = __expf(sc_[j][0] - mn0);
            sc_[j][1] = __expf(sc_[j][1] - mn0);
            sc_[j][2] = __expf(sc_[j][2] - mn1);
            sc_[j][3] = __expf(sc_[j][3] - mn1);
            rs0 += sc_[j][0] + sc_[j][1];
            rs1 += sc_[j][2] + sc_[j][3];
        }
        rs0 += __shfl_xor_sync(0xffffffffu, rs0, 1);
        rs0 += __shfl_xor_sync(0xffffffffu, rs0, 2);
        rs1 += __shfl_xor_sync(0xffffffffu, rs1, 1);
        rs1 += __shfl_xor_sync(0xffffffffu, rs1, 2);
        l0 = l0*sf0 + rs0;
        l1 = l1*sf1 + rs1;
        #pragma unroll
        for (int j = 0; j < 8; j++) {
            o[j][0] *= sf0; o[j][1] *= sf0; o[j][2] *= sf1; o[j][3] *= sf1;
        }
        // ---- P -> fp16 hi/lo A-fragments ----
        uint32_t phf[2][4], plf[2][4];
        #pragma unroll
        for (int kc = 0; kc < 2; kc++) {
            #pragma unroll
            for (int half = 0; half < 2; half++) {
                int j = 2*kc + half;
                __half h0 = __float2half_rn(sc_[j][0]);
                __half h1 = __float2half_rn(sc_[j][1]);
                __half h2 = __float2half_rn(sc_[j][2]);
                __half h3 = __float2half_rn(sc_[j][3]);
                phf[kc][half*2+0] = pack_h2(h0, h1);
                phf[kc][half*2+1] = pack_h2(h2, h3);
                plf[kc][half*2+0] = pack_h2(
                    __float2half_rn(sc_[j][0] - __half2float(h0)),
                    __float2half_rn(sc_[j][1] - __half2float(h1)));
                plf[kc][half*2+1] = pack_h2(
                    __float2half_rn(sc_[j][2] - __half2float(h2)),
                    __float2half_rn(sc_[j][3] - __half2float(h3)));
            }
        }
        // ---- O += (Ph+Pl) V16 ----
        #pragma unroll
        for (int kc = 0; kc < 2; kc++) {
            #pragma unroll
            for (int ntp = 0; ntp < 4; ntp += 2) {
                uint32_t fha[4], fhb[4];
                ldsm4t(fha, sb + KSZ + kc*16*KROW + bVoff + ntp*32);
                ldsm4t(fhb, sb + KSZ + kc*16*KROW + bVoff + (ntp+1)*32);
                mma16816(o[2*ntp],   phf[kc], fha);
                mma16816(o[2*ntp+1], phf[kc], fha+2);
                mma16816(o[2*ntp+2], phf[kc], fhb);
                mma16816(o[2*ntp+3], phf[kc], fhb+2);
                mma16816(o[2*ntp],   plf[kc], fha);
                mma16816(o[2*ntp+1], plf[kc], fha+2);
                mma16816(o[2*ntp+2], plf[kc], fhb);
                mma16816(o[2*ntp+3], plf[kc], fhb+2);
            }
        }
    }

    float inv0 = 1.f / l0, inv1 = 1.f / l1;
    size_t base0 = ((size_t)b*SS + (q0 + wr + r))*HH + h*DH;
    size_t base8 = base0 + (size_t)8*HH;
    #pragma unroll
    for (int j = 0; j < 8; j++) {
        int col = j*8 + colb;
        float a0 = o[j][0]*inv0, a1 = o[j][1]*inv0;
        float a2 = o[j][2]*inv1, a3 = o[j][3]*inv1;
        __half h0 = __float2half_rn(a0), h1 = __float2half_rn(a1);
        __half h2 = __float2half_rn(a2), h3 = __float2half_rn(a3);
        *(uint32_t*)(cth + base0 + col) = pack_h2(h0, h1);
        *(uint32_t*)(ctl + base0 + col) = pack_h2(
            __float2half_rn(a0 - __half2float(h0)),
            __float2half_rn(a1 - __half2float(h1)));
        *(uint32_t*)(cth + base8 + col) = pack_h2(h2, h3);
        *(uint32_t*)(ctl + base8 + col) = pack_h2(
            __float2half_rn(a2 - __half2float(h2)),
            __float2half_rn(a3 - __half2float(h3)));
    }
}

// ---------------- mask -> bf16 additive prebake ----------------
__global__ __launch_bounds__(256) void maskprep(const int* __restrict__ mask,
                                                __nv_bfloat16* __restrict__ madd, int n4)
{
    int i = blockIdx.x * 256 + threadIdx.x;
    if (i >= n4) return;
    int4 m = ((const int4*)mask)[i];
    __nv_bfloat16 z = __float2bfloat16(0.f), neg = __float2bfloat16(-10000.f);
    __nv_bfloat162 a = __halves2bfloat162(m.x ? z : neg, m.y ? z : neg);
    __nv_bfloat162 b = __halves2bfloat162(m.z ? z : neg, m.w ? z : neg);
    uint2 o;
    o.x = *(uint32_t*)&a; o.y = *(uint32_t*)&b;
    *(uint2*)(madd + (size_t)i*4) = o;
}

// ---------------- split fp32 -> fp16 hi/lo (only for initial x) ----------------
__global__ __launch_bounds__(256) void split_kernel(const float* __restrict__ x,
    __half* __restrict__ hi, __half* __restrict__ lo, int n4)
{
    int i = blockIdx.x * 256 + threadIdx.x;
    if (i >= n4) return;
    float4 v = ((const float4*)x)[i];
    __half h0 = __float2half_rn(v.x), h1 = __float2half_rn(v.y);
    __half h2 = __float2half_rn(v.z), h3 = __float2half_rn(v.w);
    uint2 H, L;
    H.x = pack_h2(h0, h1); H.y = pack_h2(h2, h3);
    L.x = pack_h2(__float2half_rn(v.x - __half2float(h0)),
                  __float2half_rn(v.y - __half2float(h1)));
    L.y = pack_h2(__float2half_rn(v.z - __half2float(h2)),
                  __float2half_rn(v.w - __half2float(h3)));
    *(uint2*)(hi + (size_t)i*4) = H;
    *(uint2*)(lo + (size_t)i*4) = L;
}

// ---------------- batched weight transpose (single fp16) ----------------
__global__ __launch_bounds__(256) void wtrans_all(
    const float* __restrict__ Wq, const float* __restrict__ Wk,
    const float* __restrict__ Wv, const float* __restrict__ Wao,
    const float* __restrict__ Wi, const float* __restrict__ Wfo,
    __half* __restrict__ wh)
{
    __shared__ float t[64][33];
    const int tid = threadIdx.x;
    const int l = blockIdx.z;
    int x = blockIdx.x;

    const float* W; int K_, N_; size_t off;
    if (x < 1152) {
        int m = x / 288; x -= m * 288;
        K_ = HH; N_ = HH;
        W = (m == 0 ? Wq : m == 1 ? Wk : m == 2 ? Wv : Wao) + (size_t)l * HH * HH;
        off = (m == 0 ? WQOFF : m == 1 ? WKOFF : m == 2 ? WVOFF : WAOOFF);
    } else if (x < 2304) {
        x -= 1152; K_ = HH; N_ = FF;
        W = Wi + (size_t)l * HH * FF; off = WIOFF;
    } else {
        x -= 2304; K_ = FF; N_ = HH;
        W = Wfo + (size_t)l * FF * HH; off = WFOOFF;
    }
    const int ntn = N_ >> 5;
    const int k0 = (x / ntn) << 6, n0 = (x % ntn) << 5;

    {
        int r = tid >> 5, c = tid & 31;
        #pragma unroll
        for (int i = 0; i < 8; i++)
            t[r + i*8][c] = W[(size_t)(k0 + r + i*8) * N_ + n0 + c];
    }
    __syncthreads();

    __half* hi = wh + (size_t)l * LSTRIDE + off;
    #pragma unroll
    for (int it = 0; it < 2; it++) {
        int idx = tid + it * 256;
        int nl = idx >> 4, kq = idx & 15;
        float v0 = t[kq*4+0][nl], v1 = t[kq*4+1][nl];
        float v2 = t[kq*4+2][nl], v3 = t[kq*4+3][nl];
        uint2 hv;
        hv.x = pack_h2(__float2half_rn(v0), __float2half_rn(v1));
        hv.y = pack_h2(__float2half_rn(v2), __float2half_rn(v3));
        size_t base = (size_t)(n0 + nl) * K_ + k0 + kq*4;
        *(uint2*)(hi + base) = hv;
    }
}

// ---------------- launch ----------------
extern "C" void kernel_launch(void* const* d_in, const int* in_sizes, int n_in,
                              void* d_out, int out_size)
{
    const float* x    = (const float*)d_in[0];
    const int*   mask = (const int*)  d_in[1];
    const float* Wq   = (const float*)d_in[2];
    const float* bq   = (const float*)d_in[3];
    const float* Wk   = (const float*)d_in[4];
    const float* bk   = (const float*)d_in[5];
    const float* Wv   = (const float*)d_in[6];
    const float* bv   = (const float*)d_in[7];
    const float* Wao  = (const float*)d_in[8];
    const float* bao  = (const float*)d_in[9];
    const float* g1   = (const float*)d_in[10];
    const float* b1   = (const float*)d_in[11];
    const float* Wi   = (const float*)d_in[12];
    const float* bi   = (const float*)d_in[13];
    const float* Wfo  = (const float*)d_in[14];
    const float* bfo  = (const float*)d_in[15];
    const float* g2   = (const float*)d_in[16];
    const float* b2   = (const float*)d_in[17];

    float *h_, *attn_, *p0_, *p1_, *p2_;
    __half *hh_, *hl_, *qh_, *ql_, *kh_, *kl_, *vh_, *vl_;
    __half *cth_, *ctl_, *aah_, *aal_, *ih_, *il_, *wh_;
    __nv_bfloat16 *madd_;
    cudaGetSymbolAddress((void**)&h_,    g_h);
    cudaGetSymbolAddress((void**)&attn_, g_attn);
    cudaGetSymbolAddress((void**)&p0_,   g_p0);
    cudaGetSymbolAddress((void**)&p1_,   g_p1);
    cudaGetSymbolAddress((void**)&p2_,   g_p2);
    cudaGetSymbolAddress((void**)&hh_,   g_hh);
    cudaGetSymbolAddress((void**)&hl_,   g_hl);
    cudaGetSymbolAddress((void**)&qh_,   g_qh);
    cudaGetSymbolAddress((void**)&ql_,   g_ql);
    cudaGetSymbolAddress((void**)&kh_,   g_kh);
    cudaGetSymbolAddress((void**)&kl_,   g_kl);
    cudaGetSymbolAddress((void**)&vh_,   g_vh);
    cudaGetSymbolAddress((void**)&vl_,   g_vl);
    cudaGetSymbolAddress((void**)&cth_,  g_cth);
    cudaGetSymbolAddress((void**)&ctl_,  g_ctl);
    cudaGetSymbolAddress((void**)&aah_,  g_aah);
    cudaGetSymbolAddress((void**)&aal_,  g_aal);
    cudaGetSymbolAddress((void**)&ih_,   g_ih);
    cudaGetSymbolAddress((void**)&il_,   g_il);
    cudaGetSymbolAddress((void**)&wh_,   g_wh);
    cudaGetSymbolAddress((void**)&madd_, g_madd);

    cudaFuncSetAttribute(gemm_tc,
                         cudaFuncAttributeMaxDynamicSharedMemorySize, GEMM_SMEM);
    cudaFuncSetAttribute(flashattn,
                         cudaFuncAttributeMaxDynamicSharedMemorySize, FSMEM);

    const int M = BB * SS;  // 2048
    const int n4 = M * HH / 4;
    const int mn4 = BB * SS * SS / 4;

    wtrans_all<<<dim3(3456, 1, NL), 256>>>(Wq, Wk, Wv, Wao, Wi, Wfo, wh_);
    maskprep<<<(mn4 + 255)/256, 256>>>(mask, madd_, mn4);
    split_kernel<<<(n4 + 255)/256, 256>>>(x, hh_, hl_, n4);

    for (int l = 0; l < NL; l++) {
        const float* hin = (l == 0) ? x : h_;
        size_t lo = (size_t)l * LSTRIDE;

        // QKV -> fp16 hi/lo outputs (x2)
        {
            GemmArgs a = {};
            a.ah = hh_; a.al = hl_;
            a.bh0 = wh_+lo+WQOFF; a.bh1 = wh_+lo+WKOFF; a.bh2 = wh_+lo+WVOFF;
            a.bias0 = bq + l*HH; a.bias1 = bk + l*HH; a.bias2 = bv + l*HH;
            a.ch0 = qh_; a.cl0 = ql_; a.ch1 = kh_; a.cl1 = kl_; a.ch2 = vh_; a.cl2 = vl_;
            a.K = HH; a.N = HH; a.gelu = 0; a.outbf = 1; a.Kld = HH; a.ksplit = 0; a.x1 = 0;
            gemm_tc<<<dim3(HH/128, M/128, 3), 512, GEMM_SMEM>>>(a);
        }

        flashattn<<<dim3(SS/64, BB*NH), 128, FSMEM>>>(qh_, ql_, kh_, vh_,
                                                      madd_, cth_, ctl_);

        // AO proj (x2): split-K=3 -> partials -> fused reduce+LN
        {
            GemmArgs a = {};
            a.ah = cth_; a.al = ctl_;
            a.bh0 = wh_+lo+WAOOFF; a.bh1 = a.bh0; a.bh2 = a.bh0;
            a.c0 = p0_; a.c1 = p1_; a.c2 = p2_;
            a.K = 256; a.N = HH; a.gelu = 0; a.outbf = 0; a.Kld = HH; a.ksplit = 1; a.x1 = 0;
            gemm_tc<<<dim3(HH/128, M/128, 3), 512, GEMM_SMEM>>>(a);
        }
        reduce_ln<<<M, 256>>>(p0_, p1_, p2_, bao + l*HH, hin,
                              g1 + l*HH, b1 + l*HH, attn_, aah_, aal_);

        // FFN1 (gelu, x2) -> fp16 hi/lo
        {
            GemmArgs a = {};
            a.ah = aah_; a.al = aal_;
            a.bh0 = wh_+lo+WIOFF; a.bh1 = a.bh0; a.bh2 = a.bh0;
            a.bias0 = bi + l*FF; a.bias1 = a.bias0; a.bias2 = a.bias0;
            a.ch0 = ih_; a.cl0 = il_; a.ch1 = ih_; a.cl1 = il_; a.ch2 = ih_; a.cl2 = il_;
            a.K = HH; a.N = FF; a.gelu = 1; a.outbf = 1; a.Kld = HH; a.ksplit = 0; a.x1 = 0;
            gemm_tc<<<dim3(FF/128, M/128, 1), 512, GEMM_SMEM>>>(a);
        }

        // FFN2 (x1: single fp16 activations): split-K=3 -> partials -> fused reduce+LN
        {
            GemmArgs a = {};
            a.ah = ih_; a.al = ih_;
            a.bh0 = wh_+lo+WFOOFF; a.bh1 = a.bh0; a.bh2 = a.bh0;
            a.c0 = p0_; a.c1 = p1_; a.c2 = p2_;
            a.K = 1024; a.N = HH; a.gelu = 0; a.outbf = 0; a.Kld = FF; a.ksplit = 1; a.x1 = 1;
            gemm_tc<<<dim3(HH/128, M/128, 3), 512, GEMM_SMEM>>>(a);
        }
        if (l == NL - 1) {
            reduce_ln<<<M, 256>>>(p0_, p1_, p2_, bfo + l*HH, attn_,
                                  g2 + l*HH, b2 + l*HH, (float*)d_out,
                                  (__half*)nullptr, (__half*)nullptr);
        } else {
            reduce_ln<<<M, 256>>>(p0_, p1_, p2_, bfo + l*HH, attn_,
                                  g2 + l*HH, b2 + l*HH, h_, hh_, hl_);
        }
    }
}

// round 16
// speedup vs baseline: 2.1053x; 1.4857x over previous
#include <cuda_runtime.h>
#include <cuda_bf16.h>
#include <cuda_fp16.h>
#include <math.h>
#include <stdint.h>

#define BB 2
#define SS 1024
#define HH 768
#define NH 12
#define DH 64
#define FF 3072
#define NL 4

// ---------------- scratch (device globals; no allocation allowed) ----------------
__device__ float g_h[BB*SS*HH];
__device__ float g_attn[BB*SS*HH];
__device__ float g_p0[BB*SS*HH];
__device__ float g_p1[BB*SS*HH];
__device__ float g_p2[BB*SS*HH];

__device__ __half g_hh[BB*SS*HH];
__device__ __half g_qh[BB*SS*HH];
__device__ __half g_kh[BB*SS*HH];
__device__ __half g_vh[BB*SS*HH];
__device__ __half g_cth[BB*SS*HH];
__device__ __half g_aah[BB*SS*HH];
__device__ __half g_ih[BB*SS*FF];
__device__ __nv_bfloat16 g_madd[(size_t)BB*SS*SS];   // (1-mask)*-10000 as bf16

// transposed weights per layer (single fp16): [wq wk wv wao wi wfo], each [N][K] row-major
#define WQOFF  0
#define WKOFF  589824
#define WVOFF  1179648
#define WAOOFF 1769472
#define WIOFF  2359296
#define WFOOFF 4718592
#define LSTRIDE 7077888
__device__ __half g_wh[(size_t)NL*LSTRIDE];

// ---------------- PTX helpers ----------------
__device__ __forceinline__ uint32_t smem_u32(const void* p) {
    uint32_t a;
    asm("{ .reg .u64 t; cvta.to.shared.u64 t, %1; cvt.u32.u64 %0, t; }" : "=r"(a) : "l"(p));
    return a;
}
__device__ __forceinline__ void cpa16(uint32_t dst, const void* src) {
    asm volatile("cp.async.cg.shared.global [%0], [%1], 16;" :: "r"(dst), "l"(src));
}
#define CP_COMMIT() asm volatile("cp.async.commit_group;" ::: "memory")

__device__ __forceinline__ void ldsm4(uint32_t* r, uint32_t a) {
    asm volatile("ldmatrix.sync.aligned.m8n8.x4.shared.b16 {%0,%1,%2,%3}, [%4];"
        : "=r"(r[0]), "=r"(r[1]), "=r"(r[2]), "=r"(r[3]) : "r"(a));
}
__device__ __forceinline__ void ldsm4t(uint32_t* r, uint32_t a) {
    asm volatile("ldmatrix.sync.aligned.m8n8.x4.trans.shared.b16 {%0,%1,%2,%3}, [%4];"
        : "=r"(r[0]), "=r"(r[1]), "=r"(r[2]), "=r"(r[3]) : "r"(a));
}
__device__ __forceinline__ void mma16816(float* c, const uint32_t* a, const uint32_t* b) {
    asm("mma.sync.aligned.m16n8k16.row.col.f32.f16.f16.f32 "
        "{%0,%1,%2,%3}, {%4,%5,%6,%7}, {%8,%9}, {%0,%1,%2,%3};"
        : "+f"(c[0]), "+f"(c[1]), "+f"(c[2]), "+f"(c[3])
        : "r"(a[0]), "r"(a[1]), "r"(a[2]), "r"(a[3]), "r"(b[0]), "r"(b[1]));
}
__device__ __forceinline__ uint32_t pack_h2(__half a, __half b) {
    __half2 t = __halves2half2(a, b);
    return *(uint32_t*)&t;
}

// ---------------- fp16 x1 GEMM: C = A16 @ W16^T; 128x128 tile, 512 thr, K-chunk 64,
// 2 CTAs/SM (smem 110.6KB total, 64-reg cap) ----
struct GemmArgs {
    const __half *ah;
    const __half *bh0, *bh1, *bh2;
    const float *bias0, *bias1, *bias2;
    const float *resid;
    float *c0, *c1, *c2;
    __half *ch0, *ch1, *ch2;
    int K, N, gelu, outbf, Kld, ksplit;
};

#define ROWB 144               // 128B data + 16B pad
#define ABUF 18432             // 128 rows * 144B
#define STGB (2*ABUF)          // Ah, Bh = 36864
#define NSTG 3
#define GEMM_SMEM (NSTG*STGB)  // 110592

__global__ __launch_bounds__(512, 2) void gemm_tc(GemmArgs g) {
    extern __shared__ char smem[];
    const uint32_t su = smem_u32(smem);
    const int tid = threadIdx.x;
    const int lane = tid & 31, warp = tid >> 5;
    const int warpM = warp & 3, warpN = warp >> 2;
    const int m0 = blockIdx.y << 7, n0 = blockIdx.x << 7;

    const __half *bh; const float* bias; float* C; __half *CH;
    if (blockIdx.z == 0)      { bh=g.bh0; bias=g.bias0; C=g.c0; CH=g.ch0; }
    else if (blockIdx.z == 1) { bh=g.bh1; bias=g.bias1; C=g.c1; CH=g.ch1; }
    else                      { bh=g.bh2; bias=g.bias2; C=g.c2; CH=g.ch2; }
    const int K = g.K, N = g.N, nk = K >> 6;
    const int kbase = g.ksplit ? (int)blockIdx.z * K : 0;

    const int ldg_row = tid >> 3, ldg_c = tid & 7;
    const size_t ldab = (size_t)g.Kld * 2;
    const char* pAh = (const char*)g.ah + ((size_t)(m0 + ldg_row)) * ldab + (size_t)kbase*2 + ldg_c * 16;
    const char* pBh = (const char*)bh   + ((size_t)(n0 + ldg_row)) * ldab + (size_t)kbase*2 + ldg_c * 16;
    const size_t rowskip = 64 * ldab;
    const uint32_t sdst = ldg_row * ROWB + ldg_c * 16;

    auto load_chunk = [&](int j, int s) {
        uint32_t sb = su + s * STGB + sdst;
        size_t go = (size_t)j * 128;
        cpa16(sb,                    pAh + go);
        cpa16(sb + 64*ROWB,          pAh + rowskip + go);
        cpa16(sb + ABUF,             pBh + go);
        cpa16(sb + ABUF + 64*ROWB,   pBh + rowskip + go);
    };

    load_chunk(0, 0); CP_COMMIT();
    load_chunk(1, 1); CP_COMMIT();

    float acc[2][4][4];
    #pragma unroll
    for (int i = 0; i < 2; i++)
        #pragma unroll
        for (int j = 0; j < 4; j++)
            #pragma unroll
            for (int r = 0; r < 4; r++) acc[i][j][r] = 0.f;

    const uint32_t a_off = (uint32_t)(warpM*32 + (lane & 15)) * ROWB + (lane >> 4) * 16;
    const uint32_t b_off = (uint32_t)(warpN*32 + (((lane >> 4) & 1) << 3) + (lane & 7)) * ROWB
                         + ((lane >> 3) & 1) * 16;

    for (int i = 0; i < nk; i++) {
        asm volatile("cp.async.wait_group 1;" ::: "memory");
        __syncthreads();
        int j = i + 2;
        if (j < nk) load_chunk(j, j % NSTG);
        CP_COMMIT();

        uint32_t base = su + (i % NSTG) * STGB;
        #pragma unroll
        for (int ks = 0; ks < 4; ks++) {
            uint32_t ko = ks * 32;
            uint32_t ah0[4], ah1[4], bhf0[4], bhf1[4];
            ldsm4(ah0, base + a_off + ko);
            ldsm4(ah1, base + a_off + 16*ROWB + ko);
            ldsm4(bhf0, base + ABUF + b_off + ko);
            ldsm4(bhf1, base + ABUF + b_off + 16*ROWB + ko);
            uint32_t* AH[2] = {ah0, ah1};
            #pragma unroll
            for (int mt = 0; mt < 2; mt++) {
                mma16816(acc[mt][0], AH[mt], bhf0);
                mma16816(acc[mt][1], AH[mt], bhf0+2);
                mma16816(acc[mt][2], AH[mt], bhf1);
                mma16816(acc[mt][3], AH[mt], bhf1+2);
            }
        }
    }

    const int erow = m0 + warpM*32 + (lane >> 2);
    const int ecol = n0 + warpN*32 + (lane & 3)*2;
    #pragma unroll
    for (int mt = 0; mt < 2; mt++) {
        #pragma unroll
        for (int nt = 0; nt < 4; nt++) {
            int c = ecol + nt*8;
            float b0 = bias ? bias[c] : 0.f, b1 = bias ? bias[c+1] : 0.f;
            #pragma unroll
            for (int half = 0; half < 2; half++) {
                int r = erow + mt*16 + half*8;
                float o0 = acc[mt][nt][half*2+0] + b0;
                float o1 = acc[mt][nt][half*2+1] + b1;
                if (g.resid) {
                    float2 rv = *(const float2*)(g.resid + (size_t)r * N + c);
                    o0 += rv.x; o1 += rv.y;
                }
                if (g.gelu) {
                    o0 = 0.5f * o0 * (1.0f + erff(o0 * 0.70710678118654752f));
                    o1 = 0.5f * o1 * (1.0f + erff(o1 * 0.70710678118654752f));
                }
                if (g.outbf) {
                    *(uint32_t*)(CH + (size_t)r * N + c) =
                        pack_h2(__float2half_rn(o0), __float2half_rn(o1));
                } else {
                    float2 ov; ov.x = o0; ov.y = o1;
                    *(float2*)(C + (size_t)r * N + c) = ov;
                }
            }
        }
    }
}

// ---------------- fused split-K reduce + LayerNorm (+ optional fp16 out) ----------------
__global__ __launch_bounds__(256) void reduce_ln(
    const float* __restrict__ p0, const float* __restrict__ p1,
    const float* __restrict__ p2, const float* __restrict__ bias,
    const float* __restrict__ resid,
    const float* __restrict__ g, const float* __restrict__ b,
    float* __restrict__ out, __half* __restrict__ oh)
{
    const int row = blockIdx.x;
    const int tid = threadIdx.x;
    const size_t base = (size_t)row * HH;

    float v0, v1, v2;
    {
        int i0 = tid, i1 = tid + 256, i2 = tid + 512;
        v0 = p0[base+i0] + p1[base+i0] + p2[base+i0] + bias[i0] + resid[base+i0];
        v1 = p0[base+i1] + p1[base+i1] + p2[base+i1] + bias[i1] + resid[base+i1];
        v2 = p0[base+i2] + p1[base+i2] + p2[base+i2] + bias[i2] + resid[base+i2];
    }

    __shared__ float red[8];
    float s = v0 + v1 + v2;
    #pragma unroll
    for (int o2 = 16; o2; o2 >>= 1) s += __shfl_xor_sync(0xffffffffu, s, o2);
    if ((tid & 31) == 0) red[tid >> 5] = s;
    __syncthreads();
    float tot = 0.f;
    #pragma unroll
    for (int i = 0; i < 8; i++) tot += red[i];
    float mean = tot * (1.0f / 768.0f);

    float d0 = v0 - mean, d1 = v1 - mean, d2 = v2 - mean;
    float sq = d0*d0 + d1*d1 + d2*d2;
    __syncthreads();
    #pragma unroll
    for (int o2 = 16; o2; o2 >>= 1) sq += __shfl_xor_sync(0xffffffffu, sq, o2);
    if ((tid & 31) == 0) red[tid >> 5] = sq;
    __syncthreads();
    float tot2 = 0.f;
    #pragma unroll
    for (int i = 0; i < 8; i++) tot2 += red[i];
    float rstd = rsqrtf(tot2 * (1.0f / 768.0f) + 1e-12f);

    float r0 = d0 * rstd * g[tid]       + b[tid];
    float r1 = d1 * rstd * g[tid + 256] + b[tid + 256];
    float r2 = d2 * rstd * g[tid + 512] + b[tid + 512];
    out[base + tid] = r0; out[base + tid + 256] = r1; out[base + tid + 512] = r2;
    if (oh) {
        oh[base + tid]       = __float2half_rn(r0);
        oh[base + tid + 256] = __float2half_rn(r1);
        oh[base + tid + 512] = __float2half_rn(r2);
    }
}

// ---------------- flash attention x1: all operands single fp16, fp32 accum ----
// K-tile 32, 3-stage pipeline, 5 CTAs/SM.
#define QROW 144
#define FQBUF 9216            // 64*144
#define KROW 144
#define KSZ  4608             // 32*144
#define FSTG2 (2*KSZ)         // Kh, Vh = 9216
#define FNSTG 3
#define FSMEM (FQBUF + FNSTG*FSTG2)  // 36864

__global__ __launch_bounds__(128, 5) void flashattn(
    const __half* __restrict__ qh,
    const __half* __restrict__ kh, const __half* __restrict__ vh,
    const __nv_bfloat16* __restrict__ madd,
    __half* __restrict__ cth)
{
    extern __shared__ char smem[];
    const uint32_t su = smem_u32(smem);
    const int tid = threadIdx.x, lane = tid & 31, warp = tid >> 5;
    const int q0 = blockIdx.x * 64, bh = blockIdx.y;
    const int b = bh / NH, h = bh % NH;
    const int wr = warp * 16;

    const char* Qh = (const char*)(qh + ((size_t)b*SS + q0)*HH + h*DH);
    const char* Kh = (const char*)(kh + ((size_t)b*SS)*HH + h*DH);
    const char* Vh = (const char*)(vh + ((size_t)b*SS)*HH + h*DH);

    #pragma unroll
    for (int c = 0; c < 4; c++) {
        int idx = tid + c*128;
        int row = idx >> 3, chn = idx & 7;
        uint32_t dst = su + row*QROW + chn*16;
        size_t so = (size_t)row*1536 + chn*16;
        cpa16(dst, Qh + so);
    }
    CP_COMMIT();

    auto load_kv = [&](int j, int s) {
        uint32_t sb = su + FQBUF + s*FSTG2;
        int k0 = j * 32;
        #pragma unroll
        for (int c = 0; c < 2; c++) {
            int idx = tid + c*128;
            int row = idx >> 3, chn = idx & 7;
            uint32_t dst = sb + row*KROW + chn*16;
            size_t ko = (size_t)(k0 + row)*1536 + chn*16;
            cpa16(dst,       Kh + ko);
            cpa16(dst + KSZ, Vh + ko);
        }
    };
    load_kv(0, 0); CP_COMMIT();
    load_kv(1, 1); CP_COMMIT();

    asm volatile("cp.async.wait_group 2;" ::: "memory");
    __syncthreads();

    uint32_t qhf[4][4];
    {
        uint32_t abase = su + (uint32_t)(wr + (lane & 15))*QROW + (lane >> 4)*16;
        #pragma unroll
        for (int kc = 0; kc < 4; kc++) ldsm4(qhf[kc], abase + kc*32);
    }

    float o[8][4];
    #pragma unroll
    for (int j = 0; j < 8; j++)
        #pragma unroll
        for (int r = 0; r < 4; r++) o[j][r] = 0.f;
    float m0 = -1e30f, m1 = -1e30f, l0 = 0.f, l1 = 0.f;

    const int r = lane >> 2;
    const int colb = (lane & 3) * 2;
    const __nv_bfloat16* mrow0 = madd + ((size_t)b*SS + (q0 + wr + r))*SS;
    const __nv_bfloat16* mrow8 = mrow0 + 8*SS;
    const uint32_t rowsel = (uint32_t)((((lane >> 4) & 1) << 3) + (lane & 7));
    const uint32_t bKoff = rowsel*KROW + ((lane >> 3) & 1)*16;
    const uint32_t bVoff = (uint32_t)(lane & 15)*KROW + ((lane >> 4) & 1)*16;

    for (int i = 0; i < 32; i++) {
        asm volatile("cp.async.wait_group 1;" ::: "memory");
        __syncthreads();
        if (i + 2 < 32) load_kv(i + 2, (i + 2) % 3);
        CP_COMMIT();

        const uint32_t sb = su + FQBUF + (i % 3)*FSTG2;
        const int k0 = i * 32;

        // ---- S = Q K^T ----
        float sc_[4][4];
        #pragma unroll
        for (int j = 0; j < 4; j++)
            #pragma unroll
            for (int t = 0; t < 4; t++) sc_[j][t] = 0.f;
        #pragma unroll
        for (int kc = 0; kc < 4; kc++) {
            uint32_t fh0[4], fh1[4];
            ldsm4(fh0, sb + bKoff + kc*32);
            ldsm4(fh1, sb + 16*KROW + bKoff + kc*32);
            mma16816(sc_[0], qhf[kc], fh0);
            mma16816(sc_[1], qhf[kc], fh0+2);
            mma16816(sc_[2], qhf[kc], fh1);
            mma16816(sc_[3], qhf[kc], fh1+2);
        }
        #pragma unroll
        for (int j = 0; j < 4; j++) {
            int kc2 = k0 + j*8 + colb;
            __nv_bfloat162 ma = *(const __nv_bfloat162*)(mrow0 + kc2);
            __nv_bfloat162 mb = *(const __nv_bfloat162*)(mrow8 + kc2);
            float2 fa = __bfloat1622float2(ma);
            float2 fb = __bfloat1622float2(mb);
            sc_[j][0] = sc_[j][0]*0.125f + fa.x;
            sc_[j][1] = sc_[j][1]*0.125f + fa.y;
            sc_[j][2] = sc_[j][2]*0.125f + fb.x;
            sc_[j][3] = sc_[j][3]*0.125f + fb.y;
        }
        // ---- online softmax ----
        float mx0 = -1e30f, mx1 = -1e30f;
        #pragma unroll
        for (int j = 0; j < 4; j++) {
            mx0 = fmaxf(mx0, fmaxf(sc_[j][0], sc_[j][1]));
            mx1 = fmaxf(mx1, fmaxf(sc_[j][2], sc_[j][3]));
        }
        mx0 = fmaxf(mx0, __shfl_xor_sync(0xffffffffu, mx0, 1));
        mx0 = fmaxf(mx0, __shfl_xor_sync(0xffffffffu, mx0, 2));
        mx1 = fmaxf(mx1, __shfl_xor_sync(0xffffffffu, mx1, 1));
        mx1 = fmaxf(mx1, __shfl_xor_sync(0xffffffffu, mx1, 2));
        float mn0 = fmaxf(m0, mx0), mn1 = fmaxf(m1, mx1);
        float sf0 = __expf(m0 - mn0), sf1 = __expf(m1 - mn1);
        m0 = mn0; m1 = mn1;
        float rs0 = 0.f, rs1 = 0.f;
        #pragma unroll
        for (int j = 0; j < 4; j++) {
            sc_[j][0] = __expf(sc_[j][0] - mn0);
            sc_[j][1] = __expf(sc_[j][1] - mn0);
            sc_[j][2] = __expf(sc_[j][2] - mn1);
            sc_[j][3] = __expf(sc_[j][3] - mn1);
            rs0 += sc_[j][0] + sc_[j][1];
            rs1 += sc_[j][2] + sc_[j][3];
        }
        rs0 += __shfl_xor_sync(0xffffffffu, rs0, 1);
        rs0 += __shfl_xor_sync(0xffffffffu, rs0, 2);
        rs1 += __shfl_xor_sync(0xffffffffu, rs1, 1);
        rs1 += __shfl_xor_sync(0xffffffffu, rs1, 2);
        l0 = l0*sf0 + rs0;
        l1 = l1*sf1 + rs1;
        #pragma unroll
        for (int j = 0; j < 8; j++) {
            o[j][0] *= sf0; o[j][1] *= sf0; o[j][2] *= sf1; o[j][3] *= sf1;
        }
        // ---- P -> single fp16 A-fragments ----
        uint32_t phf[2][4];
        #pragma unroll
        for (int kc = 0; kc < 2; kc++) {
            #pragma unroll
            for (int half = 0; half < 2; half++) {
                int j = 2*kc + half;
                phf[kc][half*2+0] = pack_h2(__float2half_rn(sc_[j][0]),
                                            __float2half_rn(sc_[j][1]));
                phf[kc][half*2+1] = pack_h2(__float2half_rn(sc_[j][2]),
                                            __float2half_rn(sc_[j][3]));
            }
        }
        // ---- O += P V ----
        #pragma unroll
        for (int kc = 0; kc < 2; kc++) {
            #pragma unroll
            for (int ntp = 0; ntp < 4; ntp += 2) {
                uint32_t fha[4], fhb[4];
                ldsm4t(fha, sb + KSZ + kc*16*KROW + bVoff + ntp*32);
                ldsm4t(fhb, sb + KSZ + kc*16*KROW + bVoff + (ntp+1)*32);
                mma16816(o[2*ntp],   phf[kc], fha);
                mma16816(o[2*ntp+1], phf[kc], fha+2);
                mma16816(o[2*ntp+2], phf[kc], fhb);
                mma16816(o[2*ntp+3], phf[kc], fhb+2);
            }
        }
    }

    float inv0 = 1.f / l0, inv1 = 1.f / l1;
    size_t base0 = ((size_t)b*SS + (q0 + wr + r))*HH + h*DH;
    size_t base8 = base0 + (size_t)8*HH;
    #pragma unroll
    for (int j = 0; j < 8; j++) {
        int col = j*8 + colb;
        *(uint32_t*)(cth + base0 + col) = pack_h2(__float2half_rn(o[j][0]*inv0),
                                                  __float2half_rn(o[j][1]*inv0));
        *(uint32_t*)(cth + base8 + col) = pack_h2(__float2half_rn(o[j][2]*inv1),
                                                  __float2half_rn(o[j][3]*inv1));
    }
}

// ---------------- mask -> bf16 additive prebake ----------------
__global__ __launch_bounds__(256) void maskprep(const int* __restrict__ mask,
                                                __nv_bfloat16* __restrict__ madd, int n4)
{
    int i = blockIdx.x * 256 + threadIdx.x;
    if (i >= n4) return;
    int4 m = ((const int4*)mask)[i];
    __nv_bfloat16 z = __float2bfloat16(0.f), neg = __float2bfloat16(-10000.f);
    __nv_bfloat162 a = __halves2bfloat162(m.x ? z : neg, m.y ? z : neg);
    __nv_bfloat162 b = __halves2bfloat162(m.z ? z : neg, m.w ? z : neg);
    uint2 o;
    o.x = *(uint32_t*)&a; o.y = *(uint32_t*)&b;
    *(uint2*)(madd + (size_t)i*4) = o;
}

// ---------------- convert fp32 -> fp16 (initial x only) ----------------
__global__ __launch_bounds__(256) void split_kernel(const float* __restrict__ x,
    __half* __restrict__ hi, int n4)
{
    int i = blockIdx.x * 256 + threadIdx.x;
    if (i >= n4) return;
    float4 v = ((const float4*)x)[i];
    uint2 H;
    H.x = pack_h2(__float2half_rn(v.x), __float2half_rn(v.y));
    H.y = pack_h2(__float2half_rn(v.z), __float2half_rn(v.w));
    *(uint2*)(hi + (size_t)i*4) = H;
}

// ---------------- batched weight transpose (single fp16) ----------------
__global__ __launch_bounds__(256) void wtrans_all(
    const float* __restrict__ Wq, const float* __restrict__ Wk,
    const float* __restrict__ Wv, const float* __restrict__ Wao,
    const float* __restrict__ Wi, const float* __restrict__ Wfo,
    __half* __restrict__ wh)
{
    __shared__ float t[64][33];
    const int tid = threadIdx.x;
    const int l = blockIdx.z;
    int x = blockIdx.x;

    const float* W; int K_, N_; size_t off;
    if (x < 1152) {
        int m = x / 288; x -= m * 288;
        K_ = HH; N_ = HH;
        W = (m == 0 ? Wq : m == 1 ? Wk : m == 2 ? Wv : Wao) + (size_t)l * HH * HH;
        off = (m == 0 ? WQOFF : m == 1 ? WKOFF : m == 2 ? WVOFF : WAOOFF);
    } else if (x < 2304) {
        x -= 1152; K_ = HH; N_ = FF;
        W = Wi + (size_t)l * HH * FF; off = WIOFF;
    } else {
        x -= 2304; K_ = FF; N_ = HH;
        W = Wfo + (size_t)l * FF * HH; off = WFOOFF;
    }
    const int ntn = N_ >> 5;
    const int k0 = (x / ntn) << 6, n0 = (x % ntn) << 5;

    {
        int r = tid >> 5, c = tid & 31;
        #pragma unroll
        for (int i = 0; i < 8; i++)
            t[r + i*8][c] = W[(size_t)(k0 + r + i*8) * N_ + n0 + c];
    }
    __syncthreads();

    __half* hi = wh + (size_t)l * LSTRIDE + off;
    #pragma unroll
    for (int it = 0; it < 2; it++) {
        int idx = tid + it * 256;
        int nl = idx >> 4, kq = idx & 15;
        float v0 = t[kq*4+0][nl], v1 = t[kq*4+1][nl];
        float v2 = t[kq*4+2][nl], v3 = t[kq*4+3][nl];
        uint2 hv;
        hv.x = pack_h2(__float2half_rn(v0), __float2half_rn(v1));
        hv.y = pack_h2(__float2half_rn(v2), __float2half_rn(v3));
        size_t base = (size_t)(n0 + nl) * K_ + k0 + kq*4;
        *(uint2*)(hi + base) = hv;
    }
}

// ---------------- launch ----------------
extern "C" void kernel_launch(void* const* d_in, const int* in_sizes, int n_in,
                              void* d_out, int out_size)
{
    const float* x    = (const float*)d_in[0];
    const int*   mask = (const int*)  d_in[1];
    const float* Wq   = (const float*)d_in[2];
    const float* bq   = (const float*)d_in[3];
    const float* Wk   = (const float*)d_in[4];
    const float* bk   = (const float*)d_in[5];
    const float* Wv   = (const float*)d_in[6];
    const float* bv   = (const float*)d_in[7];
    const float* Wao  = (const float*)d_in[8];
    const float* bao  = (const float*)d_in[9];
    const float* g1   = (const float*)d_in[10];
    const float* b1   = (const float*)d_in[11];
    const float* Wi   = (const float*)d_in[12];
    const float* bi   = (const float*)d_in[13];
    const float* Wfo  = (const float*)d_in[14];
    const float* bfo  = (const float*)d_in[15];
    const float* g2   = (const float*)d_in[16];
    const float* b2   = (const float*)d_in[17];

    float *h_, *attn_, *p0_, *p1_, *p2_;
    __half *hh_, *qh_, *kh_, *vh_, *cth_, *aah_, *ih_, *wh_;
    __nv_bfloat16 *madd_;
    cudaGetSymbolAddress((void**)&h_,    g_h);
    cudaGetSymbolAddress((void**)&attn_, g_attn);
    cudaGetSymbolAddress((void**)&p0_,   g_p0);
    cudaGetSymbolAddress((void**)&p1_,   g_p1);
    cudaGetSymbolAddress((void**)&p2_,   g_p2);
    cudaGetSymbolAddress((void**)&hh_,   g_hh);
    cudaGetSymbolAddress((void**)&qh_,   g_qh);
    cudaGetSymbolAddress((void**)&kh_,   g_kh);
    cudaGetSymbolAddress((void**)&vh_,   g_vh);
    cudaGetSymbolAddress((void**)&cth_,  g_cth);
    cudaGetSymbolAddress((void**)&aah_,  g_aah);
    cudaGetSymbolAddress((void**)&ih_,   g_ih);
    cudaGetSymbolAddress((void**)&wh_,   g_wh);
    cudaGetSymbolAddress((void**)&madd_, g_madd);

    cudaFuncSetAttribute(gemm_tc,
                         cudaFuncAttributeMaxDynamicSharedMemorySize, GEMM_SMEM);
    cudaFuncSetAttribute(flashattn,
                         cudaFuncAttributeMaxDynamicSharedMemorySize, FSMEM);

    const int M = BB * SS;  // 2048
    const int n4 = M * HH / 4;
    const int mn4 = BB * SS * SS / 4;

    wtrans_all<<<dim3(3456, 1, NL), 256>>>(Wq, Wk, Wv, Wao, Wi, Wfo, wh_);
    maskprep<<<(mn4 + 255)/256, 256>>>(mask, madd_, mn4);
    split_kernel<<<(n4 + 255)/256, 256>>>(x, hh_, n4);

    for (int l = 0; l < NL; l++) {
        const float* hin = (l == 0) ? x : h_;
        size_t lo = (size_t)l * LSTRIDE;

        // QKV -> fp16 outputs
        {
            GemmArgs a = {};
            a.ah = hh_;
            a.bh0 = wh_+lo+WQOFF; a.bh1 = wh_+lo+WKOFF; a.bh2 = wh_+lo+WVOFF;
            a.bias0 = bq + l*HH; a.bias1 = bk + l*HH; a.bias2 = bv + l*HH;
            a.ch0 = qh_; a.ch1 = kh_; a.ch2 = vh_;
            a.K = HH; a.N = HH; a.gelu = 0; a.outbf = 1; a.Kld = HH; a.ksplit = 0;
            gemm_tc<<<dim3(HH/128, M/128, 3), 512, GEMM_SMEM>>>(a);
        }

        flashattn<<<dim3(SS/64, BB*NH), 128, FSMEM>>>(qh_, kh_, vh_, madd_, cth_);

        // AO proj: split-K=3 -> partials -> fused reduce+LN
        {
            GemmArgs a = {};
            a.ah = cth_;
            a.bh0 = wh_+lo+WAOOFF; a.bh1 = a.bh0; a.bh2 = a.bh0;
            a.c0 = p0_; a.c1 = p1_; a.c2 = p2_;
            a.K = 256; a.N = HH; a.gelu = 0; a.outbf = 0; a.Kld = HH; a.ksplit = 1;
            gemm_tc<<<dim3(HH/128, M/128, 3), 512, GEMM_SMEM>>>(a);
        }
        reduce_ln<<<M, 256>>>(p0_, p1_, p2_, bao + l*HH, hin,
                              g1 + l*HH, b1 + l*HH, attn_, aah_);

        // FFN1 (gelu) -> fp16
        {
            GemmArgs a = {};
            a.ah = aah_;
            a.bh0 = wh_+lo+WIOFF; a.bh1 = a.bh0; a.bh2 = a.bh0;
            a.bias0 = bi + l*FF; a.bias1 = a.bias0; a.bias2 = a.bias0;
            a.ch0 = ih_; a.ch1 = ih_; a.ch2 = ih_;
            a.K = HH; a.N = FF; a.gelu = 1; a.outbf = 1; a.Kld = HH; a.ksplit = 0;
            gemm_tc<<<dim3(FF/128, M/128, 1), 512, GEMM_SMEM>>>(a);
        }

        // FFN2: split-K=3 -> partials -> fused reduce+LN
        {
            GemmArgs a = {};
            a.ah = ih_;
            a.bh0 = wh_+lo+WFOOFF; a.bh1 = a.bh0; a.bh2 = a.bh0;
            a.c0 = p0_; a.c1 = p1_; a.c2 = p2_;
            a.K = 1024; a.N = HH; a.gelu = 0; a.outbf = 0; a.Kld = FF; a.ksplit = 1;
            gemm_tc<<<dim3(HH/128, M/128, 3), 512, GEMM_SMEM>>>(a);
        }
        if (l == NL - 1) {
            reduce_ln<<<M, 256>>>(p0_, p1_, p2_, bfo + l*HH, attn_,
                                  g2 + l*HH, b2 + l*HH, (float*)d_out,
                                  (__half*)nullptr);
        } else {
            reduce_ln<<<M, 256>>>(p0_, p1_, p2_, bfo + l*HH, attn_,
                                  g2 + l*HH, b2 + l*HH, h_, hh_);
        }
    }
}